// round 1
// baseline (speedup 1.0000x reference)
#include <cuda_runtime.h>

// ---------------- problem constants ----------------
#define B_     2
#define S_     2048
#define E_     256
#define H_     8
#define DH_    256
#define INNER_ 2048      // H_*DH_
#define DFF_   1024
#define BSZ    (B_*S_)   // 4096 rows
#define EPS_   1e-6f

// ---------------- device scratch (alloc-free) ----------------
__device__ float g_q [(size_t)BSZ * INNER_];               // 32 MB
__device__ float g_k [(size_t)BSZ * INNER_];               // 32 MB
__device__ float g_v [(size_t)BSZ * INNER_];               // 32 MB
__device__ float g_sc[(size_t)B_ * H_ * S_ * S_];          // 268 MB scores
__device__ float g_o [(size_t)BSZ * INNER_];               // 32 MB
__device__ float g_t1[(size_t)BSZ * E_];                   // x + mha_out
__device__ float g_h [(size_t)BSZ * E_];                   // ln1 output
__device__ float g_ff[(size_t)BSZ * DFF_];                 // relu(h@W1+b1)
__device__ float g_t2[(size_t)BSZ * E_];                   // h + ffn

// ---------------- generic batched GEMM ----------------
// C[z] = alpha * A[z] @ op(B[z]) (+ bias) (+ resid[z]) (relu?)
// z offsets: off = (z/zdiv)*s1 + (z%zdiv)*s2 for each tensor.
#define BM 64
#define BN 64
#define BK 16
#define TM 4
#define TN 4

__global__ void gemm_kernel(
    const float* __restrict__ A, int lda,
    const float* __restrict__ Bm, int ldb, int transB,
    float* __restrict__ C, int ldc,
    int M, int N, int K,
    int zdiv,
    long long sA1, long long sA2,
    long long sB1, long long sB2,
    long long sC1, long long sC2,
    const float* __restrict__ bias,
    const float* __restrict__ resid, int ldr,
    long long sR1, long long sR2,
    float alpha, int relu)
{
    __shared__ float As[BK][BM + 1];
    __shared__ float Bs[BK][BN + 1];

    const int z  = blockIdx.z;
    const int zq = z / zdiv, zr = z % zdiv;
    A  += (long long)zq * sA1 + (long long)zr * sA2;
    Bm += (long long)zq * sB1 + (long long)zr * sB2;
    C  += (long long)zq * sC1 + (long long)zr * sC2;
    if (resid) resid += (long long)zq * sR1 + (long long)zr * sR2;

    const int bm  = blockIdx.y * BM;
    const int bn  = blockIdx.x * BN;
    const int tid = threadIdx.x;
    const int tx  = tid & 15;          // 0..15 -> N
    const int ty  = tid >> 4;          // 0..15 -> M

    float acc[TM][TN];
    #pragma unroll
    for (int i = 0; i < TM; i++)
        #pragma unroll
        for (int j = 0; j < TN; j++) acc[i][j] = 0.f;

    for (int k0 = 0; k0 < K; k0 += BK) {
        // load A tile (BM x BK), store transposed As[k][m]
        #pragma unroll
        for (int i = tid; i < BM * BK; i += 256) {
            int m  = i / BK;
            int kk = i % BK;
            As[kk][m] = A[(long long)(bm + m) * lda + (k0 + kk)];
        }
        // load B tile into Bs[k][n]
        if (!transB) {
            #pragma unroll
            for (int i = tid; i < BK * BN; i += 256) {
                int kk = i / BN;
                int n  = i % BN;
                Bs[kk][n] = Bm[(long long)(k0 + kk) * ldb + (bn + n)];
            }
        } else {
            #pragma unroll
            for (int i = tid; i < BN * BK; i += 256) {
                int n  = i / BK;
                int kk = i % BK;
                Bs[kk][n] = Bm[(long long)(bn + n) * ldb + (k0 + kk)];
            }
        }
        __syncthreads();

        #pragma unroll
        for (int kk = 0; kk < BK; kk++) {
            float af[TM], bf[TN];
            #pragma unroll
            for (int i = 0; i < TM; i++) af[i] = As[kk][ty * TM + i];
            #pragma unroll
            for (int j = 0; j < TN; j++) bf[j] = Bs[kk][tx * TN + j];
            #pragma unroll
            for (int i = 0; i < TM; i++)
                #pragma unroll
                for (int j = 0; j < TN; j++)
                    acc[i][j] += af[i] * bf[j];
        }
        __syncthreads();
    }

    // epilogue
    #pragma unroll
    for (int i = 0; i < TM; i++) {
        int m = bm + ty * TM + i;
        #pragma unroll
        for (int j = 0; j < TN; j++) {
            int n = bn + tx * TN + j;
            float v = acc[i][j] * alpha;
            if (bias)  v += bias[n];
            if (resid) v += resid[(long long)m * ldr + n];
            if (relu)  v = fmaxf(v, 0.f);
            C[(long long)m * ldc + n] = v;
        }
    }
}

// ---------------- reductions ----------------
__device__ __forceinline__ float warp_sum(float v) {
    #pragma unroll
    for (int o = 16; o > 0; o >>= 1) v += __shfl_xor_sync(0xffffffffu, v, o);
    return v;
}
__device__ __forceinline__ float warp_max(float v) {
    #pragma unroll
    for (int o = 16; o > 0; o >>= 1) v = fmaxf(v, __shfl_xor_sync(0xffffffffu, v, o));
    return v;
}

__device__ __forceinline__ float block_reduce(float v, int is_max) {
    __shared__ float sm[32];
    __shared__ float res;
    int lane = threadIdx.x & 31;
    int wid  = threadIdx.x >> 5;
    v = is_max ? warp_max(v) : warp_sum(v);
    __syncthreads();                 // protect sm across back-to-back calls
    if (lane == 0) sm[wid] = v;
    __syncthreads();
    if (wid == 0) {
        int nw = blockDim.x >> 5;
        float x = (lane < nw) ? sm[lane] : (is_max ? -1e30f : 0.f);
        x = is_max ? warp_max(x) : warp_sum(x);
        if (lane == 0) res = x;
    }
    __syncthreads();
    return res;
}

// ---------------- softmax over rows of length S_ ----------------
// grid = B*H*S rows, 256 threads, 8 elems/thread in registers, in-place.
__global__ void softmax_kernel(float* __restrict__ s)
{
    float* p = s + (long long)blockIdx.x * S_;
    const int t = threadIdx.x;
    float v[8];
    float mx = -1e30f;
    #pragma unroll
    for (int i = 0; i < 8; i++) {
        v[i] = p[t + i * 256];
        mx = fmaxf(mx, v[i]);
    }
    mx = block_reduce(mx, 1);
    float sum = 0.f;
    #pragma unroll
    for (int i = 0; i < 8; i++) {
        v[i] = __expf(v[i] - mx);
        sum += v[i];
    }
    sum = block_reduce(sum, 0);
    float inv = 1.f / sum;
    #pragma unroll
    for (int i = 0; i < 8; i++) p[t + i * 256] = v[i] * inv;
}

// ---------------- layernorm over rows of length E_ (=256=blockDim) ----------------
__global__ void ln_kernel(const float* __restrict__ x,
                          const float* __restrict__ g,
                          const float* __restrict__ b,
                          float* __restrict__ out)
{
    const int t = threadIdx.x;
    const long long base = (long long)blockIdx.x * E_;
    float v = x[base + t];
    float mean = block_reduce(v, 0) * (1.f / E_);
    float d = v - mean;
    float var = block_reduce(d * d, 0) * (1.f / E_);
    out[base + t] = d * rsqrtf(var + EPS_) * g[t] + b[t];
}

// ---------------- launch ----------------
extern "C" void kernel_launch(void* const* d_in, const int* in_sizes, int n_in,
                              void* d_out, int out_size)
{
    const float* x    = (const float*)d_in[0];
    const float* Wq   = (const float*)d_in[1];
    const float* Wk   = (const float*)d_in[2];
    const float* Wv   = (const float*)d_in[3];
    const float* Wo   = (const float*)d_in[4];
    const float* W1   = (const float*)d_in[5];
    const float* b1   = (const float*)d_in[6];
    const float* W2   = (const float*)d_in[7];
    const float* b2   = (const float*)d_in[8];
    const float* ln1g = (const float*)d_in[9];
    const float* ln1b = (const float*)d_in[10];
    const float* ln2g = (const float*)d_in[11];
    const float* ln2b = (const float*)d_in[12];

    float *q, *k, *v, *sc, *o, *t1, *h, *ff, *t2;
    cudaGetSymbolAddress((void**)&q,  g_q);
    cudaGetSymbolAddress((void**)&k,  g_k);
    cudaGetSymbolAddress((void**)&v,  g_v);
    cudaGetSymbolAddress((void**)&sc, g_sc);
    cudaGetSymbolAddress((void**)&o,  g_o);
    cudaGetSymbolAddress((void**)&t1, g_t1);
    cudaGetSymbolAddress((void**)&h,  g_h);
    cudaGetSymbolAddress((void**)&ff, g_ff);
    cudaGetSymbolAddress((void**)&t2, g_t2);

    const dim3 blk(256);
    const long long sSI = (long long)S_ * INNER_;   // per-batch stride in q/k/v/o
    const long long sSS = (long long)S_ * S_;       // per-head stride in scores

    // 1) QKV projections: [4096,256] @ [256,2048]
    {
        dim3 grd(INNER_ / BN, BSZ / BM, 1);
        gemm_kernel<<<grd, blk>>>(x, E_, Wq, INNER_, 0, q, INNER_,
                                  BSZ, INNER_, E_, 1, 0,0, 0,0, 0,0,
                                  nullptr, nullptr, 0, 0,0, 1.f, 0);
        gemm_kernel<<<grd, blk>>>(x, E_, Wk, INNER_, 0, k, INNER_,
                                  BSZ, INNER_, E_, 1, 0,0, 0,0, 0,0,
                                  nullptr, nullptr, 0, 0,0, 1.f, 0);
        gemm_kernel<<<grd, blk>>>(x, E_, Wv, INNER_, 0, v, INNER_,
                                  BSZ, INNER_, E_, 1, 0,0, 0,0, 0,0,
                                  nullptr, nullptr, 0, 0,0, 1.f, 0);
    }

    // 2) scores[z] = (Q_bh @ K_bh^T) / 16 ; z = b*H+h
    {
        dim3 grd(S_ / BN, S_ / BM, B_ * H_);
        gemm_kernel<<<grd, blk>>>(q, INNER_, k, INNER_, 1, sc, S_,
                                  S_, S_, DH_, H_,
                                  sSI, DH_,          // A offsets (b,h)
                                  sSI, DH_,          // B offsets (b,h)
                                  (long long)H_ * sSS, sSS,  // C offsets
                                  nullptr, nullptr, 0, 0,0, 1.f / 16.f, 0);
    }

    // 3) softmax rows
    softmax_kernel<<<B_ * H_ * S_, 256>>>(sc);

    // 4) O_bh = Attn_bh @ V_bh  -> g_o[b, s, h*DH + d]
    {
        dim3 grd(DH_ / BN, S_ / BM, B_ * H_);
        gemm_kernel<<<grd, blk>>>(sc, S_, v, INNER_, 0, o, INNER_,
                                  S_, DH_, S_, H_,
                                  (long long)H_ * sSS, sSS,   // A = scores
                                  sSI, DH_,                   // B = V
                                  sSI, DH_,                   // C = O
                                  nullptr, nullptr, 0, 0,0, 1.f, 0);
    }

    // 5) t1 = O @ W_o + x ; h = LN1(t1)
    {
        dim3 grd(E_ / BN, BSZ / BM, 1);
        gemm_kernel<<<grd, blk>>>(o, INNER_, Wo, E_, 0, t1, E_,
                                  BSZ, E_, INNER_, 1, 0,0, 0,0, 0,0,
                                  nullptr, x, E_, 0,0, 1.f, 0);
        ln_kernel<<<BSZ, 256>>>(t1, ln1g, ln1b, h);
    }

    // 6) ff = relu(h @ W1 + b1)
    {
        dim3 grd(DFF_ / BN, BSZ / BM, 1);
        gemm_kernel<<<grd, blk>>>(h, E_, W1, DFF_, 0, ff, DFF_,
                                  BSZ, DFF_, E_, 1, 0,0, 0,0, 0,0,
                                  b1, nullptr, 0, 0,0, 1.f, 1);
    }

    // 7) t2 = ff @ W2 + b2 + h ; out = LN2(t2)
    {
        dim3 grd(E_ / BN, BSZ / BM, 1);
        gemm_kernel<<<grd, blk>>>(ff, DFF_, W2, E_, 0, t2, E_,
                                  BSZ, E_, DFF_, 1, 0,0, 0,0, 0,0,
                                  b2, h, E_, 0,0, 1.f, 0);
        ln_kernel<<<BSZ, 256>>>(t2, ln2g, ln2b, (float*)d_out);
    }
}

// round 2
// speedup vs baseline: 2.8140x; 2.8140x over previous
#include <cuda_runtime.h>

// ---------------- problem constants ----------------
#define B_     2
#define S_     2048
#define E_     256
#define H_     8
#define DH_    256
#define INNER_ 2048      // H_*DH_
#define DFF_   1024
#define BSZ    (B_*S_)   // 4096 rows
#define EPS_   1e-6f

// ---------------- device scratch (alloc-free) ----------------
__device__ float g_q [(size_t)BSZ * INNER_];               // 32 MB
__device__ float g_k [(size_t)BSZ * INNER_];               // 32 MB
__device__ float g_v [(size_t)BSZ * INNER_];               // 32 MB
__device__ float g_sc[(size_t)B_ * H_ * S_ * S_];          // 268 MB scores
__device__ float g_o [(size_t)BSZ * INNER_];               // 32 MB
__device__ float g_t1[(size_t)BSZ * E_];
__device__ float g_h [(size_t)BSZ * E_];
__device__ float g_ff[(size_t)BSZ * DFF_];
__device__ float g_t2[(size_t)BSZ * E_];

// ---------------- high-throughput SIMT GEMM ----------------
// BM=128 x BN(128|64) tiles, BK=16, 256 threads, 8x(4*NC) microtile,
// vectorized LDS.128 reads, float4 global ld/st, register prefetch pipeline.
// C[z] = alpha * A[z] @ op(B[z]) (+ bias) (+ resid[z]) (relu?)
#define BK_ 16

template<int BN, int NC>
__global__ __launch_bounds__(256, 2)
void gemm_tc(
    const float* __restrict__ A, int lda,
    const float* __restrict__ Bm, int ldb, int transB,
    float* __restrict__ C, int ldc,
    int K,
    int zdiv,
    long long sA1, long long sA2,
    long long sB1, long long sB2,
    long long sC1, long long sC2,
    const float* __restrict__ bias,
    const float* __restrict__ resid, int ldr,
    long long sR1, long long sR2,
    float alpha, int relu)
{
    __shared__ float As[BK_][132];
    __shared__ float Bs[BK_][BN + 4];

    const int z  = blockIdx.z;
    const int zq = z / zdiv, zr = z % zdiv;
    A  += (long long)zq * sA1 + (long long)zr * sA2;
    Bm += (long long)zq * sB1 + (long long)zr * sB2;
    C  += (long long)zq * sC1 + (long long)zr * sC2;
    if (resid) resid += (long long)zq * sR1 + (long long)zr * sR2;

    const int bm  = blockIdx.y * 128;
    const int bn  = blockIdx.x * BN;
    const int tid = threadIdx.x;
    const int tx  = tid & 15;          // N strips
    const int ty  = tid >> 4;          // M strips

    // A tile loader mapping: 2 float4 per thread
    const int ar = tid >> 2;           // 0..63
    const int ak = (tid & 3) * 4;      // 0,4,8,12

    float4 acc[2][NC][4];
    #pragma unroll
    for (int r = 0; r < 2; r++)
        #pragma unroll
        for (int c = 0; c < NC; c++)
            #pragma unroll
            for (int i = 0; i < 4; i++)
                acc[r][c][i] = make_float4(0.f, 0.f, 0.f, 0.f);

    float4 pa0, pa1, pb[NC];

    // ---- prefetch tile 0 ----
    {
        pa0 = *(const float4*)&A[(long long)(bm + ar)      * lda + ak];
        pa1 = *(const float4*)&A[(long long)(bm + ar + 64) * lda + ak];
        if (!transB) {
            #pragma unroll
            for (int c = 0; c < NC; c++) {
                int idx = tid + c * 256;
                int bk  = idx / (BN / 4);
                int bn4 = idx % (BN / 4);
                pb[c] = *(const float4*)&Bm[(long long)bk * ldb + bn + bn4 * 4];
            }
        } else {
            #pragma unroll
            for (int c = 0; c < NC; c++) {
                int idx = tid + c * 256;
                int nr  = idx >> 2;
                int nk  = (idx & 3) * 4;
                pb[c] = *(const float4*)&Bm[(long long)(bn + nr) * ldb + nk];
            }
        }
    }

    for (int k0 = 0; k0 < K; k0 += BK_) {
        // ---- store prefetched tile to smem ----
        As[ak + 0][ar] = pa0.x; As[ak + 1][ar] = pa0.y;
        As[ak + 2][ar] = pa0.z; As[ak + 3][ar] = pa0.w;
        As[ak + 0][ar + 64] = pa1.x; As[ak + 1][ar + 64] = pa1.y;
        As[ak + 2][ar + 64] = pa1.z; As[ak + 3][ar + 64] = pa1.w;
        if (!transB) {
            #pragma unroll
            for (int c = 0; c < NC; c++) {
                int idx = tid + c * 256;
                int bk  = idx / (BN / 4);
                int bn4 = idx % (BN / 4);
                *(float4*)&Bs[bk][bn4 * 4] = pb[c];
            }
        } else {
            #pragma unroll
            for (int c = 0; c < NC; c++) {
                int idx = tid + c * 256;
                int nr  = idx >> 2;
                int nk  = (idx & 3) * 4;
                Bs[nk + 0][nr] = pb[c].x; Bs[nk + 1][nr] = pb[c].y;
                Bs[nk + 2][nr] = pb[c].z; Bs[nk + 3][nr] = pb[c].w;
            }
        }
        __syncthreads();

        // ---- prefetch next tile (overlaps with compute) ----
        if (k0 + BK_ < K) {
            const int kn = k0 + BK_;
            pa0 = *(const float4*)&A[(long long)(bm + ar)      * lda + kn + ak];
            pa1 = *(const float4*)&A[(long long)(bm + ar + 64) * lda + kn + ak];
            if (!transB) {
                #pragma unroll
                for (int c = 0; c < NC; c++) {
                    int idx = tid + c * 256;
                    int bk  = idx / (BN / 4);
                    int bn4 = idx % (BN / 4);
                    pb[c] = *(const float4*)&Bm[(long long)(kn + bk) * ldb + bn + bn4 * 4];
                }
            } else {
                #pragma unroll
                for (int c = 0; c < NC; c++) {
                    int idx = tid + c * 256;
                    int nr  = idx >> 2;
                    int nk  = (idx & 3) * 4;
                    pb[c] = *(const float4*)&Bm[(long long)(bn + nr) * ldb + kn + nk];
                }
            }
        }

        // ---- compute ----
        #pragma unroll
        for (int kk = 0; kk < BK_; kk++) {
            float4 a0 = *(const float4*)&As[kk][ty * 4];
            float4 a1 = *(const float4*)&As[kk][ty * 4 + 64];
            float4 b[NC];
            #pragma unroll
            for (int c = 0; c < NC; c++)
                b[c] = *(const float4*)&Bs[kk][tx * 4 + c * 64];

            #pragma unroll
            for (int c = 0; c < NC; c++) {
                float af[2][4] = {{a0.x, a0.y, a0.z, a0.w},
                                  {a1.x, a1.y, a1.z, a1.w}};
                #pragma unroll
                for (int r = 0; r < 2; r++) {
                    #pragma unroll
                    for (int i = 0; i < 4; i++) {
                        acc[r][c][i].x += af[r][i] * b[c].x;
                        acc[r][c][i].y += af[r][i] * b[c].y;
                        acc[r][c][i].z += af[r][i] * b[c].z;
                        acc[r][c][i].w += af[r][i] * b[c].w;
                    }
                }
            }
        }
        __syncthreads();
    }

    // ---- epilogue ----
    #pragma unroll
    for (int r = 0; r < 2; r++) {
        #pragma unroll
        for (int i = 0; i < 4; i++) {
            const int m = bm + ty * 4 + r * 64 + i;
            #pragma unroll
            for (int c = 0; c < NC; c++) {
                const int n = bn + tx * 4 + c * 64;
                float4 v = acc[r][c][i];
                v.x *= alpha; v.y *= alpha; v.z *= alpha; v.w *= alpha;
                if (bias) {
                    float4 bb = *(const float4*)&bias[n];
                    v.x += bb.x; v.y += bb.y; v.z += bb.z; v.w += bb.w;
                }
                if (resid) {
                    float4 rr = *(const float4*)&resid[(long long)m * ldr + n];
                    v.x += rr.x; v.y += rr.y; v.z += rr.z; v.w += rr.w;
                }
                if (relu) {
                    v.x = fmaxf(v.x, 0.f); v.y = fmaxf(v.y, 0.f);
                    v.z = fmaxf(v.z, 0.f); v.w = fmaxf(v.w, 0.f);
                }
                *(float4*)&C[(long long)m * ldc + n] = v;
            }
        }
    }
}

// ---------------- reductions ----------------
__device__ __forceinline__ float warp_sum(float v) {
    #pragma unroll
    for (int o = 16; o > 0; o >>= 1) v += __shfl_xor_sync(0xffffffffu, v, o);
    return v;
}
__device__ __forceinline__ float warp_max(float v) {
    #pragma unroll
    for (int o = 16; o > 0; o >>= 1) v = fmaxf(v, __shfl_xor_sync(0xffffffffu, v, o));
    return v;
}

__device__ __forceinline__ float block_reduce(float v, int is_max) {
    __shared__ float sm[32];
    __shared__ float res;
    int lane = threadIdx.x & 31;
    int wid  = threadIdx.x >> 5;
    v = is_max ? warp_max(v) : warp_sum(v);
    __syncthreads();
    if (lane == 0) sm[wid] = v;
    __syncthreads();
    if (wid == 0) {
        int nw = blockDim.x >> 5;
        float x = (lane < nw) ? sm[lane] : (is_max ? -1e30f : 0.f);
        x = is_max ? warp_max(x) : warp_sum(x);
        if (lane == 0) res = x;
    }
    __syncthreads();
    return res;
}

// ---------------- softmax over rows of length S_ ----------------
__global__ void softmax_kernel(float* __restrict__ s)
{
    float* p = s + (long long)blockIdx.x * S_;
    const int t = threadIdx.x;
    float v[8];
    float mx = -1e30f;
    #pragma unroll
    for (int i = 0; i < 8; i++) {
        v[i] = p[t + i * 256];
        mx = fmaxf(mx, v[i]);
    }
    mx = block_reduce(mx, 1);
    float sum = 0.f;
    #pragma unroll
    for (int i = 0; i < 8; i++) {
        v[i] = __expf(v[i] - mx);
        sum += v[i];
    }
    sum = block_reduce(sum, 0);
    float inv = 1.f / sum;
    #pragma unroll
    for (int i = 0; i < 8; i++) p[t + i * 256] = v[i] * inv;
}

// ---------------- layernorm over rows of length E_ ----------------
__global__ void ln_kernel(const float* __restrict__ x,
                          const float* __restrict__ g,
                          const float* __restrict__ b,
                          float* __restrict__ out)
{
    const int t = threadIdx.x;
    const long long base = (long long)blockIdx.x * E_;
    float v = x[base + t];
    float mean = block_reduce(v, 0) * (1.f / E_);
    float d = v - mean;
    float var = block_reduce(d * d, 0) * (1.f / E_);
    out[base + t] = d * rsqrtf(var + EPS_) * g[t] + b[t];
}

// ---------------- launch ----------------
extern "C" void kernel_launch(void* const* d_in, const int* in_sizes, int n_in,
                              void* d_out, int out_size)
{
    const float* x    = (const float*)d_in[0];
    const float* Wq   = (const float*)d_in[1];
    const float* Wk   = (const float*)d_in[2];
    const float* Wv   = (const float*)d_in[3];
    const float* Wo   = (const float*)d_in[4];
    const float* W1   = (const float*)d_in[5];
    const float* b1   = (const float*)d_in[6];
    const float* W2   = (const float*)d_in[7];
    const float* b2   = (const float*)d_in[8];
    const float* ln1g = (const float*)d_in[9];
    const float* ln1b = (const float*)d_in[10];
    const float* ln2g = (const float*)d_in[11];
    const float* ln2b = (const float*)d_in[12];

    float *q, *k, *v, *sc, *o, *t1, *h, *ff, *t2;
    cudaGetSymbolAddress((void**)&q,  g_q);
    cudaGetSymbolAddress((void**)&k,  g_k);
    cudaGetSymbolAddress((void**)&v,  g_v);
    cudaGetSymbolAddress((void**)&sc, g_sc);
    cudaGetSymbolAddress((void**)&o,  g_o);
    cudaGetSymbolAddress((void**)&t1, g_t1);
    cudaGetSymbolAddress((void**)&h,  g_h);
    cudaGetSymbolAddress((void**)&ff, g_ff);
    cudaGetSymbolAddress((void**)&t2, g_t2);

    const dim3 blk(256);
    const long long sSI = (long long)S_ * INNER_;
    const long long sSS = (long long)S_ * S_;

    // 1) QKV projections: [4096,256] @ [256,2048]
    {
        dim3 grd(INNER_ / 128, BSZ / 128, 1);
        gemm_tc<128,2><<<grd, blk>>>(x, E_, Wq, INNER_, 0, q, INNER_,
                                     E_, 1, 0,0, 0,0, 0,0,
                                     nullptr, nullptr, 0, 0,0, 1.f, 0);
        gemm_tc<128,2><<<grd, blk>>>(x, E_, Wk, INNER_, 0, k, INNER_,
                                     E_, 1, 0,0, 0,0, 0,0,
                                     nullptr, nullptr, 0, 0,0, 1.f, 0);
        gemm_tc<128,2><<<grd, blk>>>(x, E_, Wv, INNER_, 0, v, INNER_,
                                     E_, 1, 0,0, 0,0, 0,0,
                                     nullptr, nullptr, 0, 0,0, 1.f, 0);
    }

    // 2) scores[z] = (Q_bh @ K_bh^T) / 16 ; z = b*H+h
    {
        dim3 grd(S_ / 128, S_ / 128, B_ * H_);
        gemm_tc<128,2><<<grd, blk>>>(q, INNER_, k, INNER_, 1, sc, S_,
                                     DH_, H_,
                                     sSI, DH_,
                                     sSI, DH_,
                                     (long long)H_ * sSS, sSS,
                                     nullptr, nullptr, 0, 0,0, 1.f / 16.f, 0);
    }

    // 3) softmax rows
    softmax_kernel<<<B_ * H_ * S_, 256>>>(sc);

    // 4) O_bh = Attn_bh @ V_bh
    {
        dim3 grd(DH_ / 128, S_ / 128, B_ * H_);
        gemm_tc<128,2><<<grd, blk>>>(sc, S_, v, INNER_, 0, o, INNER_,
                                     S_, H_,
                                     (long long)H_ * sSS, sSS,
                                     sSI, DH_,
                                     sSI, DH_,
                                     nullptr, nullptr, 0, 0,0, 1.f, 0);
    }

    // 5) t1 = O @ W_o + x ; h = LN1(t1)   (skinny N=256 -> BN=64, 128 CTAs)
    {
        dim3 grd(E_ / 64, BSZ / 128, 1);
        gemm_tc<64,1><<<grd, blk>>>(o, INNER_, Wo, E_, 0, t1, E_,
                                    INNER_, 1, 0,0, 0,0, 0,0,
                                    nullptr, x, E_, 0,0, 1.f, 0);
        ln_kernel<<<BSZ, 256>>>(t1, ln1g, ln1b, h);
    }

    // 6) ff = relu(h @ W1 + b1)
    {
        dim3 grd(DFF_ / 128, BSZ / 128, 1);
        gemm_tc<128,2><<<grd, blk>>>(h, E_, W1, DFF_, 0, ff, DFF_,
                                     E_, 1, 0,0, 0,0, 0,0,
                                     b1, nullptr, 0, 0,0, 1.f, 1);
    }

    // 7) t2 = ff @ W2 + b2 + h ; out = LN2(t2)  (skinny N=256 -> BN=64)
    {
        dim3 grd(E_ / 64, BSZ / 128, 1);
        gemm_tc<64,1><<<grd, blk>>>(ff, DFF_, W2, E_, 0, t2, E_,
                                    DFF_, 1, 0,0, 0,0, 0,0,
                                    b2, h, E_, 0,0, 1.f, 0);
        ln_kernel<<<BSZ, 256>>>(t2, ln2g, ln2b, (float*)d_out);
    }
}

// round 4
// speedup vs baseline: 5.0150x; 1.7822x over previous
#include <cuda_runtime.h>
#include <cuda_bf16.h>
#include <cstdint>

// ---------------- problem constants ----------------
#define B_     2
#define S_     2048
#define E_     256
#define H_     8
#define DH_    256
#define INNER_ 2048      // H_*DH_
#define DFF_   1024
#define BSZ    (B_*S_)   // 4096 rows
#define EPS_   1e-6f

typedef __nv_bfloat16 bf16;

// ---------------- device scratch (alloc-free) ----------------
__device__ bf16  g_xh [(size_t)BSZ * E_];
__device__ bf16  g_xl [(size_t)BSZ * E_];
__device__ bf16  g_wqT_h[(size_t)INNER_ * E_];
__device__ bf16  g_wqT_l[(size_t)INNER_ * E_];
__device__ bf16  g_wkT_h[(size_t)INNER_ * E_];
__device__ bf16  g_wkT_l[(size_t)INNER_ * E_];
__device__ bf16  g_wvT_h[(size_t)INNER_ * E_];
__device__ bf16  g_wvT_l[(size_t)INNER_ * E_];
__device__ bf16  g_woT_h[(size_t)E_ * INNER_];
__device__ bf16  g_woT_l[(size_t)E_ * INNER_];
__device__ bf16  g_w1T_h[(size_t)DFF_ * E_];
__device__ bf16  g_w1T_l[(size_t)DFF_ * E_];
__device__ bf16  g_w2T_h[(size_t)E_ * DFF_];
__device__ bf16  g_w2T_l[(size_t)E_ * DFF_];
__device__ bf16  g_qh [(size_t)BSZ * INNER_];
__device__ bf16  g_ql [(size_t)BSZ * INNER_];
__device__ bf16  g_kh [(size_t)BSZ * INNER_];
__device__ bf16  g_kl [(size_t)BSZ * INNER_];
__device__ bf16  g_vh [(size_t)BSZ * INNER_];
__device__ bf16  g_vl [(size_t)BSZ * INNER_];
__device__ bf16  g_vth[(size_t)BSZ * INNER_];   // V^T per (b,h): [B*H][DH][S]
__device__ bf16  g_vtl[(size_t)BSZ * INNER_];
__device__ float g_sc [(size_t)B_ * H_ * S_ * S_];   // fp32 scores
__device__ bf16  g_ph [(size_t)B_ * H_ * S_ * S_];   // probs hi
__device__ bf16  g_pl [(size_t)B_ * H_ * S_ * S_];   // probs lo
__device__ bf16  g_oh [(size_t)BSZ * INNER_];
__device__ bf16  g_ol [(size_t)BSZ * INNER_];
__device__ float g_t1 [(size_t)BSZ * E_];
__device__ float g_hf [(size_t)BSZ * E_];
__device__ bf16  g_hh [(size_t)BSZ * E_];
__device__ bf16  g_hl [(size_t)BSZ * E_];
__device__ bf16  g_ffh[(size_t)BSZ * DFF_];
__device__ bf16  g_ffl[(size_t)BSZ * DFF_];
__device__ float g_t2 [(size_t)BSZ * E_];

// ---------------- warp-MMA helpers (family-portable PTX only) ----------------
__device__ __forceinline__ uint32_t smem_u32(const void* p) {
    uint32_t a;
    asm("{ .reg .u64 t; cvta.to.shared.u64 t, %1; cvt.u32.u64 %0, t; }"
        : "=r"(a) : "l"(p));
    return a;
}

__device__ __forceinline__ void ldsm_x4(uint32_t* r, uint32_t a) {
    asm volatile("ldmatrix.sync.aligned.m8n8.x4.shared.b16 {%0,%1,%2,%3}, [%4];"
                 : "=r"(r[0]), "=r"(r[1]), "=r"(r[2]), "=r"(r[3]) : "r"(a));
}

__device__ __forceinline__ void mma16816(float* c, const uint32_t* a,
                                         uint32_t b0, uint32_t b1) {
    asm volatile(
        "mma.sync.aligned.m16n8k16.row.col.f32.bf16.bf16.f32 "
        "{%0,%1,%2,%3}, {%4,%5,%6,%7}, {%8,%9}, {%0,%1,%2,%3};"
        : "+f"(c[0]), "+f"(c[1]), "+f"(c[2]), "+f"(c[3])
        : "r"(a[0]), "r"(a[1]), "r"(a[2]), "r"(a[3]), "r"(b0), "r"(b1));
}

// ---------------- bf16x3 HMMA GEMM ----------------
// D[128,128] = alpha * (Ah+Al)[M,K] @ (Bh+Bl)[N,K]^T  (3-term split, fp32 acc)
// A, B K-major row-major bf16. Output fp32 or bf16 hi/lo split.
#define KB_   32
#define ASTR  80     // smem row stride bytes (64 data + 16 pad) -> conflict-free ldmatrix

template<int OUT_SPLIT>
__global__ void __launch_bounds__(256)
gemm_hmma3(const bf16* __restrict__ Ah, const bf16* __restrict__ Al, int lda,
           const bf16* __restrict__ Bh, const bf16* __restrict__ Bl, int ldb,
           float* __restrict__ Cf, bf16* __restrict__ Ch, bf16* __restrict__ Cl, int ldc,
           int K, int zdiv,
           long long sA1, long long sA2,
           long long sB1, long long sB2,
           long long sC1, long long sC2,
           const float* __restrict__ bias,
           const float* __restrict__ resid, int ldr,
           float alpha, int relu)
{
    __shared__ __align__(16) char sAh[128 * ASTR];
    __shared__ __align__(16) char sAl[128 * ASTR];
    __shared__ __align__(16) char sBh[128 * ASTR];
    __shared__ __align__(16) char sBl[128 * ASTR];

    const int z  = blockIdx.z;
    const int zq = z / zdiv, zr = z % zdiv;
    const long long aoff = (long long)zq * sA1 + (long long)zr * sA2;
    const long long boff = (long long)zq * sB1 + (long long)zr * sB2;
    const long long coff = (long long)zq * sC1 + (long long)zr * sC2;
    Ah += aoff; Al += aoff;
    Bh += boff; Bl += boff;
    if (Cf) Cf += coff;
    if (Ch) { Ch += coff; Cl += coff; }

    const int bm   = blockIdx.y * 128;
    const int bn   = blockIdx.x * 128;
    const int tid  = threadIdx.x;
    const int wid  = tid >> 5;
    const int lane = tid & 31;
    const int wm   = (wid & 1) * 64;   // warp m offset in tile
    const int wn   = (wid >> 1) * 32;  // warp n offset in tile

    // loader mapping: idx = tid + it*256 ; row = idx>>2 ; chunk c = idx&3 (16B chunks)
    const int lrow0 = tid >> 2;
    const int lrow1 = (tid + 256) >> 2;
    const int lc0   = tid & 3;

    // smem base addresses (u32, shared space)
    const uint32_t uAh = smem_u32(sAh);
    const uint32_t uAl = smem_u32(sAl);
    const uint32_t uBh = smem_u32(sBh);
    const uint32_t uBl = smem_u32(sBl);

    // ldmatrix per-thread invariants
    const uint32_t aBase = (uint32_t)((wm + (lane & 15)) * ASTR + (lane >> 4) * 16);
    const uint32_t bBase = (uint32_t)((wn + (lane & 7) + ((lane >> 4) & 1) * 8) * ASTR
                                      + (lane & 8) * 2);

    float acc[4][4][4];
    #pragma unroll
    for (int mt = 0; mt < 4; mt++)
        #pragma unroll
        for (int nt = 0; nt < 4; nt++)
            #pragma unroll
            for (int i = 0; i < 4; i++) acc[mt][nt][i] = 0.f;

    uint4 pAh[2], pAl[2], pBh[2], pBl[2];

    // prefetch k-block 0
    {
        const long long ga0 = (long long)(bm + lrow0) * lda + lc0 * 8;
        const long long ga1 = (long long)(bm + lrow1) * lda + lc0 * 8;
        const long long gb0 = (long long)(bn + lrow0) * ldb + lc0 * 8;
        const long long gb1 = (long long)(bn + lrow1) * ldb + lc0 * 8;
        pAh[0] = *(const uint4*)(Ah + ga0); pAh[1] = *(const uint4*)(Ah + ga1);
        pAl[0] = *(const uint4*)(Al + ga0); pAl[1] = *(const uint4*)(Al + ga1);
        pBh[0] = *(const uint4*)(Bh + gb0); pBh[1] = *(const uint4*)(Bh + gb1);
        pBl[0] = *(const uint4*)(Bl + gb0); pBl[1] = *(const uint4*)(Bl + gb1);
    }

    const int nkb = K / KB_;
    for (int kb = 0; kb < nkb; kb++) {
        // store prefetched tiles
        const int so0 = lrow0 * ASTR + lc0 * 16;
        const int so1 = lrow1 * ASTR + lc0 * 16;
        *(uint4*)(sAh + so0) = pAh[0]; *(uint4*)(sAh + so1) = pAh[1];
        *(uint4*)(sAl + so0) = pAl[0]; *(uint4*)(sAl + so1) = pAl[1];
        *(uint4*)(sBh + so0) = pBh[0]; *(uint4*)(sBh + so1) = pBh[1];
        *(uint4*)(sBl + so0) = pBl[0]; *(uint4*)(sBl + so1) = pBl[1];
        __syncthreads();

        // prefetch next k-block
        if (kb + 1 < nkb) {
            const int kn = (kb + 1) * KB_;
            const long long ga0 = (long long)(bm + lrow0) * lda + kn + lc0 * 8;
            const long long ga1 = (long long)(bm + lrow1) * lda + kn + lc0 * 8;
            const long long gb0 = (long long)(bn + lrow0) * ldb + kn + lc0 * 8;
            const long long gb1 = (long long)(bn + lrow1) * ldb + kn + lc0 * 8;
            pAh[0] = *(const uint4*)(Ah + ga0); pAh[1] = *(const uint4*)(Ah + ga1);
            pAl[0] = *(const uint4*)(Al + ga0); pAl[1] = *(const uint4*)(Al + ga1);
            pBh[0] = *(const uint4*)(Bh + gb0); pBh[1] = *(const uint4*)(Bh + gb1);
            pBl[0] = *(const uint4*)(Bl + gb0); pBl[1] = *(const uint4*)(Bl + gb1);
        }

        // compute: 2 k-steps of 16
        #pragma unroll
        for (int ks = 0; ks < 2; ks++) {
            const uint32_t ksb = ks * 32;   // 16 bf16 = 32 bytes
            uint32_t ah[4][4], al[4][4];
            #pragma unroll
            for (int mt = 0; mt < 4; mt++) {
                ldsm_x4(ah[mt], uAh + aBase + mt * (16 * ASTR) + ksb);
                ldsm_x4(al[mt], uAl + aBase + mt * (16 * ASTR) + ksb);
            }
            uint32_t bh[2][4], bl[2][4];
            #pragma unroll
            for (int g = 0; g < 2; g++) {
                ldsm_x4(bh[g], uBh + bBase + g * (16 * ASTR) + ksb);
                ldsm_x4(bl[g], uBl + bBase + g * (16 * ASTR) + ksb);
            }
            #pragma unroll
            for (int mt = 0; mt < 4; mt++) {
                #pragma unroll
                for (int nt = 0; nt < 4; nt++) {
                    const uint32_t b0h = bh[nt >> 1][(nt & 1) * 2];
                    const uint32_t b1h = bh[nt >> 1][(nt & 1) * 2 + 1];
                    const uint32_t b0l = bl[nt >> 1][(nt & 1) * 2];
                    const uint32_t b1l = bl[nt >> 1][(nt & 1) * 2 + 1];
                    mma16816(acc[mt][nt], ah[mt], b0h, b1h);
                    mma16816(acc[mt][nt], ah[mt], b0l, b1l);
                    mma16816(acc[mt][nt], al[mt], b0h, b1h);
                }
            }
        }
        __syncthreads();
    }

    // ---- epilogue ----
    const int er = lane >> 2;
    const int ec = (lane & 3) * 2;
    #pragma unroll
    for (int mt = 0; mt < 4; mt++) {
        #pragma unroll
        for (int half = 0; half < 2; half++) {
            const int m = bm + wm + mt * 16 + er + half * 8;
            #pragma unroll
            for (int nt = 0; nt < 4; nt++) {
                const int n = bn + wn + nt * 8 + ec;
                float v0 = acc[mt][nt][half * 2 + 0] * alpha;
                float v1 = acc[mt][nt][half * 2 + 1] * alpha;
                if (bias) { v0 += __ldg(&bias[n]); v1 += __ldg(&bias[n + 1]); }
                if (resid) {
                    float2 rr = *(const float2*)&resid[(long long)m * ldr + n];
                    v0 += rr.x; v1 += rr.y;
                }
                if (relu) { v0 = fmaxf(v0, 0.f); v1 = fmaxf(v1, 0.f); }
                if (OUT_SPLIT) {
                    __nv_bfloat162 hi2 = __floats2bfloat162_rn(v0, v1);
                    float l0 = v0 - __bfloat162float(__low2bfloat16(hi2));
                    float l1 = v1 - __bfloat162float(__high2bfloat16(hi2));
                    __nv_bfloat162 lo2 = __floats2bfloat162_rn(l0, l1);
                    *(uint32_t*)&Ch[(long long)m * ldc + n] = *(uint32_t*)&hi2;
                    *(uint32_t*)&Cl[(long long)m * ldc + n] = *(uint32_t*)&lo2;
                } else {
                    *(float2*)&Cf[(long long)m * ldc + n] = make_float2(v0, v1);
                }
            }
        }
    }
}

// ---------------- reductions ----------------
__device__ __forceinline__ float warp_sum(float v) {
    #pragma unroll
    for (int o = 16; o > 0; o >>= 1) v += __shfl_xor_sync(0xffffffffu, v, o);
    return v;
}
__device__ __forceinline__ float warp_max(float v) {
    #pragma unroll
    for (int o = 16; o > 0; o >>= 1) v = fmaxf(v, __shfl_xor_sync(0xffffffffu, v, o));
    return v;
}
__device__ __forceinline__ float block_reduce(float v, int is_max) {
    __shared__ float sm[32];
    __shared__ float res;
    int lane = threadIdx.x & 31;
    int wid  = threadIdx.x >> 5;
    v = is_max ? warp_max(v) : warp_sum(v);
    __syncthreads();
    if (lane == 0) sm[wid] = v;
    __syncthreads();
    if (wid == 0) {
        int nw = blockDim.x >> 5;
        float x = (lane < nw) ? sm[lane] : (is_max ? -1e30f : 0.f);
        x = is_max ? warp_max(x) : warp_sum(x);
        if (lane == 0) res = x;
    }
    __syncthreads();
    return res;
}

// ---------------- softmax: fp32 scores -> bf16 hi/lo probs ----------------
__global__ void softmax_kernel(const float* __restrict__ s,
                               bf16* __restrict__ ph, bf16* __restrict__ pl)
{
    const long long base = (long long)blockIdx.x * S_;
    const int t = threadIdx.x;
    float v[8];
    float mx = -1e30f;
    #pragma unroll
    for (int i = 0; i < 8; i++) {
        v[i] = s[base + t + i * 256];
        mx = fmaxf(mx, v[i]);
    }
    mx = block_reduce(mx, 1);
    float sum = 0.f;
    #pragma unroll
    for (int i = 0; i < 8; i++) {
        v[i] = __expf(v[i] - mx);
        sum += v[i];
    }
    sum = block_reduce(sum, 0);
    float inv = 1.f / sum;
    #pragma unroll
    for (int i = 0; i < 8; i++) {
        float p = v[i] * inv;
        bf16 hi = __float2bfloat16(p);
        float lo = p - __bfloat162float(hi);
        ph[base + t + i * 256] = hi;
        pl[base + t + i * 256] = __float2bfloat16(lo);
    }
}

// ---------------- layernorm (+ optional bf16 split output) ----------------
__global__ void ln_kernel(const float* __restrict__ x,
                          const float* __restrict__ g,
                          const float* __restrict__ b,
                          float* __restrict__ outf,
                          bf16* __restrict__ oh, bf16* __restrict__ ol)
{
    const int t = threadIdx.x;
    const long long base = (long long)blockIdx.x * E_;
    float v = x[base + t];
    float mean = block_reduce(v, 0) * (1.f / E_);
    float d = v - mean;
    float var = block_reduce(d * d, 0) * (1.f / E_);
    float r = d * rsqrtf(var + EPS_) * g[t] + b[t];
    if (outf) outf[base + t] = r;
    if (oh) {
        bf16 hi = __float2bfloat16(r);
        oh[base + t] = hi;
        ol[base + t] = __float2bfloat16(r - __bfloat162float(hi));
    }
}

// ---------------- elementwise fp32 -> bf16 hi/lo split ----------------
__global__ void split_kernel(const float* __restrict__ in,
                             bf16* __restrict__ oh, bf16* __restrict__ ol, int n)
{
    int i = blockIdx.x * blockDim.x + threadIdx.x;
    if (i < n) {
        float f = in[i];
        bf16 hi = __float2bfloat16(f);
        oh[i] = hi;
        ol[i] = __float2bfloat16(f - __bfloat162float(hi));
    }
}

// ---------------- weight transpose + split: W[R][C] -> WT_h/l[C][R] ----------------
__global__ void wsplitT_kernel(const float* __restrict__ W, int R, int C,
                               bf16* __restrict__ oh, bf16* __restrict__ ol)
{
    __shared__ float t[32][33];
    const int c0 = blockIdx.x * 32;
    const int r0 = blockIdx.y * 32;
    const int tx = threadIdx.x, ty = threadIdx.y;
    #pragma unroll
    for (int j = 0; j < 4; j++) {
        int r = ty + 8 * j;
        t[r][tx] = W[(long long)(r0 + r) * C + c0 + tx];
    }
    __syncthreads();
    #pragma unroll
    for (int j = 0; j < 4; j++) {
        int r = ty + 8 * j;
        float f = t[tx][r];
        bf16 hi = __float2bfloat16(f);
        long long o = (long long)(c0 + r) * R + r0 + tx;
        oh[o] = hi;
        ol[o] = __float2bfloat16(f - __bfloat162float(hi));
    }
}

// ---------------- V transpose (bf16 hi+lo): v[b,s,h*DH+d] -> vt[(b*H+h)][d][s] ----
__global__ void vtrans_kernel(const bf16* __restrict__ vh, const bf16* __restrict__ vl,
                              bf16* __restrict__ vth, bf16* __restrict__ vtl)
{
    __shared__ bf16 th[32][33];
    __shared__ bf16 tl[32][33];
    const int z = blockIdx.z;            // b*H + h
    const int b = z / H_, h = z % H_;
    const int s0 = blockIdx.x * 32;
    const int d0 = blockIdx.y * 32;
    const int tx = threadIdx.x, ty = threadIdx.y;
    const long long ibase = (long long)b * S_ * INNER_ + (long long)h * DH_;
    const long long obase = (long long)z * DH_ * S_;
    #pragma unroll
    for (int j = 0; j < 4; j++) {
        int r = ty + 8 * j;
        long long ia = ibase + (long long)(s0 + r) * INNER_ + d0 + tx;
        th[r][tx] = vh[ia];
        tl[r][tx] = vl[ia];
    }
    __syncthreads();
    #pragma unroll
    for (int j = 0; j < 4; j++) {
        int r = ty + 8 * j;
        long long oa = obase + (long long)(d0 + r) * S_ + s0 + tx;
        vth[oa] = th[tx][r];
        vtl[oa] = tl[tx][r];
    }
}

// ---------------- launch ----------------
extern "C" void kernel_launch(void* const* d_in, const int* in_sizes, int n_in,
                              void* d_out, int out_size)
{
    const float* x    = (const float*)d_in[0];
    const float* Wq   = (const float*)d_in[1];
    const float* Wk   = (const float*)d_in[2];
    const float* Wv   = (const float*)d_in[3];
    const float* Wo   = (const float*)d_in[4];
    const float* W1   = (const float*)d_in[5];
    const float* b1   = (const float*)d_in[6];
    const float* W2   = (const float*)d_in[7];
    const float* b2   = (const float*)d_in[8];
    const float* ln1g = (const float*)d_in[9];
    const float* ln1b = (const float*)d_in[10];
    const float* ln2g = (const float*)d_in[11];
    const float* ln2b = (const float*)d_in[12];

    #define SYM(p, s) p; cudaGetSymbolAddress((void**)&p, s)
    bf16 *SYM(xh, g_xh); bf16 *SYM(xl, g_xl);
    bf16 *SYM(wqh, g_wqT_h); bf16 *SYM(wql, g_wqT_l);
    bf16 *SYM(wkh, g_wkT_h); bf16 *SYM(wkl, g_wkT_l);
    bf16 *SYM(wvh, g_wvT_h); bf16 *SYM(wvl, g_wvT_l);
    bf16 *SYM(woh, g_woT_h); bf16 *SYM(wol, g_woT_l);
    bf16 *SYM(w1h, g_w1T_h); bf16 *SYM(w1l, g_w1T_l);
    bf16 *SYM(w2h, g_w2T_h); bf16 *SYM(w2l, g_w2T_l);
    bf16 *SYM(qh, g_qh); bf16 *SYM(ql, g_ql);
    bf16 *SYM(kh, g_kh); bf16 *SYM(kl, g_kl);
    bf16 *SYM(vh, g_vh); bf16 *SYM(vl, g_vl);
    bf16 *SYM(vth, g_vth); bf16 *SYM(vtl, g_vtl);
    float *SYM(sc, g_sc);
    bf16 *SYM(ph, g_ph); bf16 *SYM(pl, g_pl);
    bf16 *SYM(oh, g_oh); bf16 *SYM(ol, g_ol);
    float *SYM(t1, g_t1); float *SYM(hf, g_hf);
    bf16 *SYM(hh, g_hh); bf16 *SYM(hl, g_hl);
    bf16 *SYM(ffh, g_ffh); bf16 *SYM(ffl, g_ffl);
    float *SYM(t2, g_t2);

    const long long sSI = (long long)S_ * INNER_;
    const long long sSS = (long long)S_ * S_;
    const dim3 blk(256);
    const dim3 tblk(32, 8);

    // 0) splits / transposed weight conversion
    split_kernel<<<(BSZ * E_ + 255) / 256, 256>>>(x, xh, xl, BSZ * E_);
    { dim3 g(INNER_/32, E_/32);  wsplitT_kernel<<<g, tblk>>>(Wq, E_, INNER_, wqh, wql); }
    { dim3 g(INNER_/32, E_/32);  wsplitT_kernel<<<g, tblk>>>(Wk, E_, INNER_, wkh, wkl); }
    { dim3 g(INNER_/32, E_/32);  wsplitT_kernel<<<g, tblk>>>(Wv, E_, INNER_, wvh, wvl); }
    { dim3 g(E_/32, INNER_/32);  wsplitT_kernel<<<g, tblk>>>(Wo, INNER_, E_, woh, wol); }
    { dim3 g(DFF_/32, E_/32);    wsplitT_kernel<<<g, tblk>>>(W1, E_, DFF_, w1h, w1l); }
    { dim3 g(E_/32, DFF_/32);    wsplitT_kernel<<<g, tblk>>>(W2, DFF_, E_, w2h, w2l); }

    // 1) QKV projections: [4096,256] @ [256,2048] -> split outputs
    {
        dim3 grd(INNER_/128, BSZ/128, 1);
        gemm_hmma3<1><<<grd, blk>>>(xh, xl, E_, wqh, wql, E_,
            nullptr, qh, ql, INNER_, E_, 1, 0,0, 0,0, 0,0,
            nullptr, nullptr, 0, 1.f, 0);
        gemm_hmma3<1><<<grd, blk>>>(xh, xl, E_, wkh, wkl, E_,
            nullptr, kh, kl, INNER_, E_, 1, 0,0, 0,0, 0,0,
            nullptr, nullptr, 0, 1.f, 0);
        gemm_hmma3<1><<<grd, blk>>>(xh, xl, E_, wvh, wvl, E_,
            nullptr, vh, vl, INNER_, E_, 1, 0,0, 0,0, 0,0,
            nullptr, nullptr, 0, 1.f, 0);
    }

    // V^T per (b,h)
    { dim3 g(S_/32, DH_/32, B_*H_); vtrans_kernel<<<g, tblk>>>(vh, vl, vth, vtl); }

    // 2) scores = Q @ K^T / 16  (fp32 out)
    {
        dim3 grd(S_/128, S_/128, B_*H_);
        gemm_hmma3<0><<<grd, blk>>>(qh, ql, INNER_, kh, kl, INNER_,
            sc, nullptr, nullptr, S_, DH_, H_,
            sSI, DH_, sSI, DH_, (long long)H_*sSS, sSS,
            nullptr, nullptr, 0, 1.f/16.f, 0);
    }

    // 3) softmax -> probs hi/lo
    softmax_kernel<<<B_*H_*S_, 256>>>(sc, ph, pl);

    // 4) O = P @ V   (B operand = V^T, K-major)
    {
        dim3 grd(DH_/128, S_/128, B_*H_);
        gemm_hmma3<1><<<grd, blk>>>(ph, pl, S_, vth, vtl, S_,
            nullptr, oh, ol, INNER_, S_, H_,
            (long long)H_*sSS, sSS,
            (long long)H_*(long long)DH_*S_, (long long)DH_*S_,
            sSI, DH_,
            nullptr, nullptr, 0, 1.f, 0);
    }

    // 5) t1 = O @ Wo + x ; h = LN1(t1)  (h also split)
    {
        dim3 grd(E_/128, BSZ/128, 1);
        gemm_hmma3<0><<<grd, blk>>>(oh, ol, INNER_, woh, wol, INNER_,
            t1, nullptr, nullptr, E_, INNER_, 1, 0,0, 0,0, 0,0,
            nullptr, x, E_, 1.f, 0);
        ln_kernel<<<BSZ, 256>>>(t1, ln1g, ln1b, hf, hh, hl);
    }

    // 6) ff = relu(h @ W1 + b1)  (split out)
    {
        dim3 grd(DFF_/128, BSZ/128, 1);
        gemm_hmma3<1><<<grd, blk>>>(hh, hl, E_, w1h, w1l, E_,
            nullptr, ffh, ffl, DFF_, E_, 1, 0,0, 0,0, 0,0,
            b1, nullptr, 0, 1.f, 1);
    }

    // 7) t2 = ff @ W2 + b2 + h ; out = LN2(t2)
    {
        dim3 grd(E_/128, BSZ/128, 1);
        gemm_hmma3<0><<<grd, blk>>>(ffh, ffl, DFF_, w2h, w2l, DFF_,
            t2, nullptr, nullptr, E_, DFF_, 1, 0,0, 0,0, 0,0,
            b2, hf, E_, 1.f, 0);
        ln_kernel<<<BSZ, 256>>>(t2, ln2g, ln2b, (float*)d_out, nullptr, nullptr);
    }
}

// round 5
// speedup vs baseline: 5.0207x; 1.0011x over previous
#include <cuda_runtime.h>
#include <cuda_bf16.h>
#include <cstdint>

// ---------------- problem constants ----------------
#define B_     2
#define S_     2048
#define E_     256
#define H_     8
#define DH_    256
#define INNER_ 2048      // H_*DH_
#define DFF_   1024
#define BSZ    (B_*S_)   // 4096 rows
#define EPS_   1e-6f

typedef __nv_bfloat16 bf16;

// ---------------- device scratch (alloc-free) ----------------
__device__ bf16  g_xh [(size_t)BSZ * E_];
__device__ bf16  g_xl [(size_t)BSZ * E_];
__device__ bf16  g_wqT_h[(size_t)INNER_ * E_];
__device__ bf16  g_wqT_l[(size_t)INNER_ * E_];
__device__ bf16  g_wkT_h[(size_t)INNER_ * E_];
__device__ bf16  g_wkT_l[(size_t)INNER_ * E_];
__device__ bf16  g_wvT_h[(size_t)INNER_ * E_];
__device__ bf16  g_wvT_l[(size_t)INNER_ * E_];
__device__ bf16  g_woT_h[(size_t)E_ * INNER_];
__device__ bf16  g_woT_l[(size_t)E_ * INNER_];
__device__ bf16  g_w1T_h[(size_t)DFF_ * E_];
__device__ bf16  g_w1T_l[(size_t)DFF_ * E_];
__device__ bf16  g_w2T_h[(size_t)E_ * DFF_];
__device__ bf16  g_w2T_l[(size_t)E_ * DFF_];
__device__ bf16  g_qh [(size_t)BSZ * INNER_];
__device__ bf16  g_ql [(size_t)BSZ * INNER_];
__device__ bf16  g_kh [(size_t)BSZ * INNER_];
__device__ bf16  g_kl [(size_t)BSZ * INNER_];
__device__ bf16  g_vh [(size_t)BSZ * INNER_];
__device__ bf16  g_vl [(size_t)BSZ * INNER_];
__device__ bf16  g_vth[(size_t)BSZ * INNER_];   // V^T per (b,h): [B*H][DH][S]
__device__ bf16  g_vtl[(size_t)BSZ * INNER_];
__device__ float g_sc [(size_t)B_ * H_ * S_ * S_];   // fp32 scores
__device__ bf16  g_ph [(size_t)B_ * H_ * S_ * S_];   // probs hi
__device__ bf16  g_pl [(size_t)B_ * H_ * S_ * S_];   // probs lo
__device__ bf16  g_oh [(size_t)BSZ * INNER_];
__device__ bf16  g_ol [(size_t)BSZ * INNER_];
__device__ float g_t1 [(size_t)BSZ * E_];
__device__ float g_hf [(size_t)BSZ * E_];
__device__ bf16  g_hh [(size_t)BSZ * E_];
__device__ bf16  g_hl [(size_t)BSZ * E_];
__device__ bf16  g_ffh[(size_t)BSZ * DFF_];
__device__ bf16  g_ffl[(size_t)BSZ * DFF_];
__device__ float g_t2 [(size_t)BSZ * E_];

// ---------------- warp-MMA helpers (family-portable PTX only) ----------------
__device__ __forceinline__ uint32_t smem_u32(const void* p) {
    uint32_t a;
    asm("{ .reg .u64 t; cvta.to.shared.u64 t, %1; cvt.u32.u64 %0, t; }"
        : "=r"(a) : "l"(p));
    return a;
}

__device__ __forceinline__ void ldsm_x4(uint32_t* r, uint32_t a) {
    asm volatile("ldmatrix.sync.aligned.m8n8.x4.shared.b16 {%0,%1,%2,%3}, [%4];"
                 : "=r"(r[0]), "=r"(r[1]), "=r"(r[2]), "=r"(r[3]) : "r"(a));
}

__device__ __forceinline__ void mma16816(float* c, const uint32_t* a,
                                         uint32_t b0, uint32_t b1) {
    asm volatile(
        "mma.sync.aligned.m16n8k16.row.col.f32.bf16.bf16.f32 "
        "{%0,%1,%2,%3}, {%4,%5,%6,%7}, {%8,%9}, {%0,%1,%2,%3};"
        : "+f"(c[0]), "+f"(c[1]), "+f"(c[2]), "+f"(c[3])
        : "r"(a[0]), "r"(a[1]), "r"(a[2]), "r"(a[3]), "r"(b0), "r"(b1));
}

// ---------------- bf16x3 HMMA GEMM ----------------
// D[128,128] = alpha * (Ah+Al)[M,K] @ (Bh+Bl)[N,K]^T  (3-term split, fp32 acc)
// A, B K-major row-major bf16. Output fp32 or bf16 hi/lo split.
#define KB_   32
#define ASTR  80     // smem row stride bytes (64 data + 16 pad) -> conflict-free ldmatrix

template<int OUT_SPLIT>
__global__ void __launch_bounds__(256)
gemm_hmma3(const bf16* __restrict__ Ah, const bf16* __restrict__ Al, int lda,
           const bf16* __restrict__ Bh, const bf16* __restrict__ Bl, int ldb,
           float* __restrict__ Cf, bf16* __restrict__ Ch, bf16* __restrict__ Cl, int ldc,
           int K, int zdiv,
           long long sA1, long long sA2,
           long long sB1, long long sB2,
           long long sC1, long long sC2,
           const float* __restrict__ bias,
           const float* __restrict__ resid, int ldr,
           float alpha, int relu)
{
    __shared__ __align__(16) char sAh[128 * ASTR];
    __shared__ __align__(16) char sAl[128 * ASTR];
    __shared__ __align__(16) char sBh[128 * ASTR];
    __shared__ __align__(16) char sBl[128 * ASTR];

    const int z  = blockIdx.z;
    const int zq = z / zdiv, zr = z % zdiv;
    const long long aoff = (long long)zq * sA1 + (long long)zr * sA2;
    const long long boff = (long long)zq * sB1 + (long long)zr * sB2;
    const long long coff = (long long)zq * sC1 + (long long)zr * sC2;
    Ah += aoff; Al += aoff;
    Bh += boff; Bl += boff;
    if (Cf) Cf += coff;
    if (Ch) { Ch += coff; Cl += coff; }

    const int bm   = blockIdx.y * 128;
    const int bn   = blockIdx.x * 128;
    const int tid  = threadIdx.x;
    const int wid  = tid >> 5;
    const int lane = tid & 31;
    const int wm   = (wid & 1) * 64;   // warp m offset in tile
    const int wn   = (wid >> 1) * 32;  // warp n offset in tile

    // loader mapping: idx = tid + it*256 ; row = idx>>2 ; chunk c = idx&3 (16B chunks)
    const int lrow0 = tid >> 2;
    const int lrow1 = (tid + 256) >> 2;
    const int lc0   = tid & 3;

    // smem base addresses (u32, shared space)
    const uint32_t uAh = smem_u32(sAh);
    const uint32_t uAl = smem_u32(sAl);
    const uint32_t uBh = smem_u32(sBh);
    const uint32_t uBl = smem_u32(sBl);

    // ldmatrix per-thread invariants
    const uint32_t aBase = (uint32_t)((wm + (lane & 15)) * ASTR + (lane >> 4) * 16);
    const uint32_t bBase = (uint32_t)((wn + (lane & 7) + ((lane >> 4) & 1) * 8) * ASTR
                                      + (lane & 8) * 2);

    float acc[4][4][4];
    #pragma unroll
    for (int mt = 0; mt < 4; mt++)
        #pragma unroll
        for (int nt = 0; nt < 4; nt++)
            #pragma unroll
            for (int i = 0; i < 4; i++) acc[mt][nt][i] = 0.f;

    uint4 pAh[2], pAl[2], pBh[2], pBl[2];

    // prefetch k-block 0
    {
        const long long ga0 = (long long)(bm + lrow0) * lda + lc0 * 8;
        const long long ga1 = (long long)(bm + lrow1) * lda + lc0 * 8;
        const long long gb0 = (long long)(bn + lrow0) * ldb + lc0 * 8;
        const long long gb1 = (long long)(bn + lrow1) * ldb + lc0 * 8;
        pAh[0] = *(const uint4*)(Ah + ga0); pAh[1] = *(const uint4*)(Ah + ga1);
        pAl[0] = *(const uint4*)(Al + ga0); pAl[1] = *(const uint4*)(Al + ga1);
        pBh[0] = *(const uint4*)(Bh + gb0); pBh[1] = *(const uint4*)(Bh + gb1);
        pBl[0] = *(const uint4*)(Bl + gb0); pBl[1] = *(const uint4*)(Bl + gb1);
    }

    const int nkb = K / KB_;
    for (int kb = 0; kb < nkb; kb++) {
        // store prefetched tiles
        const int so0 = lrow0 * ASTR + lc0 * 16;
        const int so1 = lrow1 * ASTR + lc0 * 16;
        *(uint4*)(sAh + so0) = pAh[0]; *(uint4*)(sAh + so1) = pAh[1];
        *(uint4*)(sAl + so0) = pAl[0]; *(uint4*)(sAl + so1) = pAl[1];
        *(uint4*)(sBh + so0) = pBh[0]; *(uint4*)(sBh + so1) = pBh[1];
        *(uint4*)(sBl + so0) = pBl[0]; *(uint4*)(sBl + so1) = pBl[1];
        __syncthreads();

        // prefetch next k-block
        if (kb + 1 < nkb) {
            const int kn = (kb + 1) * KB_;
            const long long ga0 = (long long)(bm + lrow0) * lda + kn + lc0 * 8;
            const long long ga1 = (long long)(bm + lrow1) * lda + kn + lc0 * 8;
            const long long gb0 = (long long)(bn + lrow0) * ldb + kn + lc0 * 8;
            const long long gb1 = (long long)(bn + lrow1) * ldb + kn + lc0 * 8;
            pAh[0] = *(const uint4*)(Ah + ga0); pAh[1] = *(const uint4*)(Ah + ga1);
            pAl[0] = *(const uint4*)(Al + ga0); pAl[1] = *(const uint4*)(Al + ga1);
            pBh[0] = *(const uint4*)(Bh + gb0); pBh[1] = *(const uint4*)(Bh + gb1);
            pBl[0] = *(const uint4*)(Bl + gb0); pBl[1] = *(const uint4*)(Bl + gb1);
        }

        // compute: 2 k-steps of 16
        #pragma unroll
        for (int ks = 0; ks < 2; ks++) {
            const uint32_t ksb = ks * 32;   // 16 bf16 = 32 bytes
            uint32_t ah[4][4], al[4][4];
            #pragma unroll
            for (int mt = 0; mt < 4; mt++) {
                ldsm_x4(ah[mt], uAh + aBase + mt * (16 * ASTR) + ksb);
                ldsm_x4(al[mt], uAl + aBase + mt * (16 * ASTR) + ksb);
            }
            uint32_t bh[2][4], bl[2][4];
            #pragma unroll
            for (int g = 0; g < 2; g++) {
                ldsm_x4(bh[g], uBh + bBase + g * (16 * ASTR) + ksb);
                ldsm_x4(bl[g], uBl + bBase + g * (16 * ASTR) + ksb);
            }
            #pragma unroll
            for (int mt = 0; mt < 4; mt++) {
                #pragma unroll
                for (int nt = 0; nt < 4; nt++) {
                    const uint32_t b0h = bh[nt >> 1][(nt & 1) * 2];
                    const uint32_t b1h = bh[nt >> 1][(nt & 1) * 2 + 1];
                    const uint32_t b0l = bl[nt >> 1][(nt & 1) * 2];
                    const uint32_t b1l = bl[nt >> 1][(nt & 1) * 2 + 1];
                    mma16816(acc[mt][nt], ah[mt], b0h, b1h);
                    mma16816(acc[mt][nt], ah[mt], b0l, b1l);
                    mma16816(acc[mt][nt], al[mt], b0h, b1h);
                }
            }
        }
        __syncthreads();
    }

    // ---- epilogue ----
    const int er = lane >> 2;
    const int ec = (lane & 3) * 2;
    #pragma unroll
    for (int mt = 0; mt < 4; mt++) {
        #pragma unroll
        for (int half = 0; half < 2; half++) {
            const int m = bm + wm + mt * 16 + er + half * 8;
            #pragma unroll
            for (int nt = 0; nt < 4; nt++) {
                const int n = bn + wn + nt * 8 + ec;
                float v0 = acc[mt][nt][half * 2 + 0] * alpha;
                float v1 = acc[mt][nt][half * 2 + 1] * alpha;
                if (bias) { v0 += __ldg(&bias[n]); v1 += __ldg(&bias[n + 1]); }
                if (resid) {
                    float2 rr = *(const float2*)&resid[(long long)m * ldr + n];
                    v0 += rr.x; v1 += rr.y;
                }
                if (relu) { v0 = fmaxf(v0, 0.f); v1 = fmaxf(v1, 0.f); }
                if (OUT_SPLIT) {
                    __nv_bfloat162 hi2 = __floats2bfloat162_rn(v0, v1);
                    float l0 = v0 - __bfloat162float(__low2bfloat16(hi2));
                    float l1 = v1 - __bfloat162float(__high2bfloat16(hi2));
                    __nv_bfloat162 lo2 = __floats2bfloat162_rn(l0, l1);
                    *(uint32_t*)&Ch[(long long)m * ldc + n] = *(uint32_t*)&hi2;
                    *(uint32_t*)&Cl[(long long)m * ldc + n] = *(uint32_t*)&lo2;
                } else {
                    *(float2*)&Cf[(long long)m * ldc + n] = make_float2(v0, v1);
                }
            }
        }
    }
}

// ---------------- reductions ----------------
__device__ __forceinline__ float warp_sum(float v) {
    #pragma unroll
    for (int o = 16; o > 0; o >>= 1) v += __shfl_xor_sync(0xffffffffu, v, o);
    return v;
}
__device__ __forceinline__ float warp_max(float v) {
    #pragma unroll
    for (int o = 16; o > 0; o >>= 1) v = fmaxf(v, __shfl_xor_sync(0xffffffffu, v, o));
    return v;
}
__device__ __forceinline__ float block_reduce(float v, int is_max) {
    __shared__ float sm[32];
    __shared__ float res;
    int lane = threadIdx.x & 31;
    int wid  = threadIdx.x >> 5;
    v = is_max ? warp_max(v) : warp_sum(v);
    __syncthreads();
    if (lane == 0) sm[wid] = v;
    __syncthreads();
    if (wid == 0) {
        int nw = blockDim.x >> 5;
        float x = (lane < nw) ? sm[lane] : (is_max ? -1e30f : 0.f);
        x = is_max ? warp_max(x) : warp_sum(x);
        if (lane == 0) res = x;
    }
    __syncthreads();
    return res;
}

// ---------------- softmax: fp32 scores -> bf16 hi/lo probs ----------------
__global__ void softmax_kernel(const float* __restrict__ s,
                               bf16* __restrict__ ph, bf16* __restrict__ pl)
{
    const long long base = (long long)blockIdx.x * S_;
    const int t = threadIdx.x;
    float v[8];
    float mx = -1e30f;
    #pragma unroll
    for (int i = 0; i < 8; i++) {
        v[i] = s[base + t + i * 256];
        mx = fmaxf(mx, v[i]);
    }
    mx = block_reduce(mx, 1);
    float sum = 0.f;
    #pragma unroll
    for (int i = 0; i < 8; i++) {
        v[i] = __expf(v[i] - mx);
        sum += v[i];
    }
    sum = block_reduce(sum, 0);
    float inv = 1.f / sum;
    #pragma unroll
    for (int i = 0; i < 8; i++) {
        float p = v[i] * inv;
        bf16 hi = __float2bfloat16(p);
        float lo = p - __bfloat162float(hi);
        ph[base + t + i * 256] = hi;
        pl[base + t + i * 256] = __float2bfloat16(lo);
    }
}

// ---------------- layernorm (+ optional bf16 split output) ----------------
__global__ void ln_kernel(const float* __restrict__ x,
                          const float* __restrict__ g,
                          const float* __restrict__ b,
                          float* __restrict__ outf,
                          bf16* __restrict__ oh, bf16* __restrict__ ol)
{
    const int t = threadIdx.x;
    const long long base = (long long)blockIdx.x * E_;
    float v = x[base + t];
    float mean = block_reduce(v, 0) * (1.f / E_);
    float d = v - mean;
    float var = block_reduce(d * d, 0) * (1.f / E_);
    float r = d * rsqrtf(var + EPS_) * g[t] + b[t];
    if (outf) outf[base + t] = r;
    if (oh) {
        bf16 hi = __float2bfloat16(r);
        oh[base + t] = hi;
        ol[base + t] = __float2bfloat16(r - __bfloat162float(hi));
    }
}

// ---------------- elementwise fp32 -> bf16 hi/lo split ----------------
__global__ void split_kernel(const float* __restrict__ in,
                             bf16* __restrict__ oh, bf16* __restrict__ ol, int n)
{
    int i = blockIdx.x * blockDim.x + threadIdx.x;
    if (i < n) {
        float f = in[i];
        bf16 hi = __float2bfloat16(f);
        oh[i] = hi;
        ol[i] = __float2bfloat16(f - __bfloat162float(hi));
    }
}

// ---------------- weight transpose + split: W[R][C] -> WT_h/l[C][R] ----------------
__global__ void wsplitT_kernel(const float* __restrict__ W, int R, int C,
                               bf16* __restrict__ oh, bf16* __restrict__ ol)
{
    __shared__ float t[32][33];
    const int c0 = blockIdx.x * 32;
    const int r0 = blockIdx.y * 32;
    const int tx = threadIdx.x, ty = threadIdx.y;
    #pragma unroll
    for (int j = 0; j < 4; j++) {
        int r = ty + 8 * j;
        t[r][tx] = W[(long long)(r0 + r) * C + c0 + tx];
    }
    __syncthreads();
    #pragma unroll
    for (int j = 0; j < 4; j++) {
        int r = ty + 8 * j;
        float f = t[tx][r];
        bf16 hi = __float2bfloat16(f);
        long long o = (long long)(c0 + r) * R + r0 + tx;
        oh[o] = hi;
        ol[o] = __float2bfloat16(f - __bfloat162float(hi));
    }
}

// ---------------- V transpose (bf16 hi+lo): v[b,s,h*DH+d] -> vt[(b*H+h)][d][s] ----
__global__ void vtrans_kernel(const bf16* __restrict__ vh, const bf16* __restrict__ vl,
                              bf16* __restrict__ vth, bf16* __restrict__ vtl)
{
    __shared__ bf16 th[32][33];
    __shared__ bf16 tl[32][33];
    const int z = blockIdx.z;            // b*H + h
    const int b = z / H_, h = z % H_;
    const int s0 = blockIdx.x * 32;
    const int d0 = blockIdx.y * 32;
    const int tx = threadIdx.x, ty = threadIdx.y;
    const long long ibase = (long long)b * S_ * INNER_ + (long long)h * DH_;
    const long long obase = (long long)z * DH_ * S_;
    #pragma unroll
    for (int j = 0; j < 4; j++) {
        int r = ty + 8 * j;
        long long ia = ibase + (long long)(s0 + r) * INNER_ + d0 + tx;
        th[r][tx] = vh[ia];
        tl[r][tx] = vl[ia];
    }
    __syncthreads();
    #pragma unroll
    for (int j = 0; j < 4; j++) {
        int r = ty + 8 * j;
        long long oa = obase + (long long)(d0 + r) * S_ + s0 + tx;
        vth[oa] = th[tx][r];
        vtl[oa] = tl[tx][r];
    }
}

// ---------------- launch ----------------
extern "C" void kernel_launch(void* const* d_in, const int* in_sizes, int n_in,
                              void* d_out, int out_size)
{
    const float* x    = (const float*)d_in[0];
    const float* Wq   = (const float*)d_in[1];
    const float* Wk   = (const float*)d_in[2];
    const float* Wv   = (const float*)d_in[3];
    const float* Wo   = (const float*)d_in[4];
    const float* W1   = (const float*)d_in[5];
    const float* b1   = (const float*)d_in[6];
    const float* W2   = (const float*)d_in[7];
    const float* b2   = (const float*)d_in[8];
    const float* ln1g = (const float*)d_in[9];
    const float* ln1b = (const float*)d_in[10];
    const float* ln2g = (const float*)d_in[11];
    const float* ln2b = (const float*)d_in[12];

    #define SYM(p, s) p; cudaGetSymbolAddress((void**)&p, s)
    bf16 *SYM(xh, g_xh); bf16 *SYM(xl, g_xl);
    bf16 *SYM(wqh, g_wqT_h); bf16 *SYM(wql, g_wqT_l);
    bf16 *SYM(wkh, g_wkT_h); bf16 *SYM(wkl, g_wkT_l);
    bf16 *SYM(wvh, g_wvT_h); bf16 *SYM(wvl, g_wvT_l);
    bf16 *SYM(woh, g_woT_h); bf16 *SYM(wol, g_woT_l);
    bf16 *SYM(w1h, g_w1T_h); bf16 *SYM(w1l, g_w1T_l);
    bf16 *SYM(w2h, g_w2T_h); bf16 *SYM(w2l, g_w2T_l);
    bf16 *SYM(qh, g_qh); bf16 *SYM(ql, g_ql);
    bf16 *SYM(kh, g_kh); bf16 *SYM(kl, g_kl);
    bf16 *SYM(vh, g_vh); bf16 *SYM(vl, g_vl);
    bf16 *SYM(vth, g_vth); bf16 *SYM(vtl, g_vtl);
    float *SYM(sc, g_sc);
    bf16 *SYM(ph, g_ph); bf16 *SYM(pl, g_pl);
    bf16 *SYM(oh, g_oh); bf16 *SYM(ol, g_ol);
    float *SYM(t1, g_t1); float *SYM(hf, g_hf);
    bf16 *SYM(hh, g_hh); bf16 *SYM(hl, g_hl);
    bf16 *SYM(ffh, g_ffh); bf16 *SYM(ffl, g_ffl);
    float *SYM(t2, g_t2);

    const long long sSI = (long long)S_ * INNER_;
    const long long sSS = (long long)S_ * S_;
    const dim3 blk(256);
    const dim3 tblk(32, 8);

    // 0) splits / transposed weight conversion
    split_kernel<<<(BSZ * E_ + 255) / 256, 256>>>(x, xh, xl, BSZ * E_);
    { dim3 g(INNER_/32, E_/32);  wsplitT_kernel<<<g, tblk>>>(Wq, E_, INNER_, wqh, wql); }
    { dim3 g(INNER_/32, E_/32);  wsplitT_kernel<<<g, tblk>>>(Wk, E_, INNER_, wkh, wkl); }
    { dim3 g(INNER_/32, E_/32);  wsplitT_kernel<<<g, tblk>>>(Wv, E_, INNER_, wvh, wvl); }
    { dim3 g(E_/32, INNER_/32);  wsplitT_kernel<<<g, tblk>>>(Wo, INNER_, E_, woh, wol); }
    { dim3 g(DFF_/32, E_/32);    wsplitT_kernel<<<g, tblk>>>(W1, E_, DFF_, w1h, w1l); }
    { dim3 g(E_/32, DFF_/32);    wsplitT_kernel<<<g, tblk>>>(W2, DFF_, E_, w2h, w2l); }

    // 1) QKV projections: [4096,256] @ [256,2048] -> split outputs
    {
        dim3 grd(INNER_/128, BSZ/128, 1);
        gemm_hmma3<1><<<grd, blk>>>(xh, xl, E_, wqh, wql, E_,
            nullptr, qh, ql, INNER_, E_, 1, 0,0, 0,0, 0,0,
            nullptr, nullptr, 0, 1.f, 0);
        gemm_hmma3<1><<<grd, blk>>>(xh, xl, E_, wkh, wkl, E_,
            nullptr, kh, kl, INNER_, E_, 1, 0,0, 0,0, 0,0,
            nullptr, nullptr, 0, 1.f, 0);
        gemm_hmma3<1><<<grd, blk>>>(xh, xl, E_, wvh, wvl, E_,
            nullptr, vh, vl, INNER_, E_, 1, 0,0, 0,0, 0,0,
            nullptr, nullptr, 0, 1.f, 0);
    }

    // V^T per (b,h)
    { dim3 g(S_/32, DH_/32, B_*H_); vtrans_kernel<<<g, tblk>>>(vh, vl, vth, vtl); }

    // 2) scores = Q @ K^T / 16  (fp32 out)
    {
        dim3 grd(S_/128, S_/128, B_*H_);
        gemm_hmma3<0><<<grd, blk>>>(qh, ql, INNER_, kh, kl, INNER_,
            sc, nullptr, nullptr, S_, DH_, H_,
            sSI, DH_, sSI, DH_, (long long)H_*sSS, sSS,
            nullptr, nullptr, 0, 1.f/16.f, 0);
    }

    // 3) softmax -> probs hi/lo
    softmax_kernel<<<B_*H_*S_, 256>>>(sc, ph, pl);

    // 4) O = P @ V   (B operand = V^T, K-major)
    {
        dim3 grd(DH_/128, S_/128, B_*H_);
        gemm_hmma3<1><<<grd, blk>>>(ph, pl, S_, vth, vtl, S_,
            nullptr, oh, ol, INNER_, S_, H_,
            (long long)H_*sSS, sSS,
            (long long)H_*(long long)DH_*S_, (long long)DH_*S_,
            sSI, DH_,
            nullptr, nullptr, 0, 1.f, 0);
    }

    // 5) t1 = O @ Wo + x ; h = LN1(t1)  (h also split)
    {
        dim3 grd(E_/128, BSZ/128, 1);
        gemm_hmma3<0><<<grd, blk>>>(oh, ol, INNER_, woh, wol, INNER_,
            t1, nullptr, nullptr, E_, INNER_, 1, 0,0, 0,0, 0,0,
            nullptr, x, E_, 1.f, 0);
        ln_kernel<<<BSZ, 256>>>(t1, ln1g, ln1b, hf, hh, hl);
    }

    // 6) ff = relu(h @ W1 + b1)  (split out)
    {
        dim3 grd(DFF_/128, BSZ/128, 1);
        gemm_hmma3<1><<<grd, blk>>>(hh, hl, E_, w1h, w1l, E_,
            nullptr, ffh, ffl, DFF_, E_, 1, 0,0, 0,0, 0,0,
            b1, nullptr, 0, 1.f, 1);
    }

    // 7) t2 = ff @ W2 + b2 + h ; out = LN2(t2)
    {
        dim3 grd(E_/128, BSZ/128, 1);
        gemm_hmma3<0><<<grd, blk>>>(ffh, ffl, DFF_, w2h, w2l, DFF_,
            t2, nullptr, nullptr, E_, DFF_, 1, 0,0, 0,0, 0,0,
            b2, hf, E_, 1.f, 0);
        ln_kernel<<<BSZ, 256>>>(t2, ln2g, ln2b, (float*)d_out, nullptr, nullptr);
    }
}

// round 6
// speedup vs baseline: 6.0536x; 1.2057x over previous
#include <cuda_runtime.h>
#include <cuda_bf16.h>
#include <cstdint>

#define B_     2
#define S_     2048
#define E_     256
#define H_     8
#define DH_    256
#define INNER_ 2048
#define DFF_   1024
#define BSZ    (B_*S_)
#define EPS_   1e-6f

typedef __nv_bfloat16 bf16;

// ---------------- device scratch ----------------
__device__ bf16  g_xh [(size_t)BSZ * E_];
__device__ bf16  g_xl [(size_t)BSZ * E_];
__device__ bf16  g_wqT_h[(size_t)INNER_ * E_];
__device__ bf16  g_wqT_l[(size_t)INNER_ * E_];
__device__ bf16  g_wkT_h[(size_t)INNER_ * E_];
__device__ bf16  g_wkT_l[(size_t)INNER_ * E_];
__device__ bf16  g_wvT_h[(size_t)INNER_ * E_];
__device__ bf16  g_wvT_l[(size_t)INNER_ * E_];
__device__ bf16  g_woT_h[(size_t)E_ * INNER_];
__device__ bf16  g_woT_l[(size_t)E_ * INNER_];
__device__ bf16  g_w1T_h[(size_t)DFF_ * E_];
__device__ bf16  g_w1T_l[(size_t)DFF_ * E_];
__device__ bf16  g_w2T_h[(size_t)E_ * DFF_];
__device__ bf16  g_w2T_l[(size_t)E_ * DFF_];
__device__ bf16  g_qh [(size_t)BSZ * INNER_];
__device__ bf16  g_ql [(size_t)BSZ * INNER_];
__device__ bf16  g_kh [(size_t)BSZ * INNER_];
__device__ bf16  g_kl [(size_t)BSZ * INNER_];
__device__ bf16  g_vh [(size_t)BSZ * INNER_];
__device__ bf16  g_vl [(size_t)BSZ * INNER_];
__device__ bf16  g_vth[(size_t)BSZ * INNER_];   // V^T per (b,h): [B*H][DH][S]
__device__ bf16  g_vtl[(size_t)BSZ * INNER_];
__device__ bf16  g_oh [(size_t)BSZ * INNER_];
__device__ bf16  g_ol [(size_t)BSZ * INNER_];
__device__ float g_t1 [(size_t)BSZ * E_];
__device__ float g_hf [(size_t)BSZ * E_];
__device__ bf16  g_hh [(size_t)BSZ * E_];
__device__ bf16  g_hl [(size_t)BSZ * E_];
__device__ bf16  g_ffh[(size_t)BSZ * DFF_];
__device__ bf16  g_ffl[(size_t)BSZ * DFF_];
__device__ float g_t2 [(size_t)BSZ * E_];

// ---------------- helpers ----------------
__device__ __forceinline__ uint32_t smem_u32(const void* p) {
    uint32_t a;
    asm("{ .reg .u64 t; cvta.to.shared.u64 t, %1; cvt.u32.u64 %0, t; }"
        : "=r"(a) : "l"(p));
    return a;
}
__device__ __forceinline__ void ldsm_x4(uint32_t* r, uint32_t a) {
    asm volatile("ldmatrix.sync.aligned.m8n8.x4.shared.b16 {%0,%1,%2,%3}, [%4];"
                 : "=r"(r[0]), "=r"(r[1]), "=r"(r[2]), "=r"(r[3]) : "r"(a));
}
__device__ __forceinline__ void mma16816(float* c, const uint32_t* a,
                                         uint32_t b0, uint32_t b1) {
    asm volatile(
        "mma.sync.aligned.m16n8k16.row.col.f32.bf16.bf16.f32 "
        "{%0,%1,%2,%3}, {%4,%5,%6,%7}, {%8,%9}, {%0,%1,%2,%3};"
        : "+f"(c[0]), "+f"(c[1]), "+f"(c[2]), "+f"(c[3])
        : "r"(a[0]), "r"(a[1]), "r"(a[2]), "r"(a[3]), "r"(b0), "r"(b1));
}
#define CP16(dst, src) \
    asm volatile("cp.async.cg.shared.global [%0], [%1], 16;" :: "r"(dst), "l"(src) : "memory")
#define CP_COMMIT  asm volatile("cp.async.commit_group;" ::: "memory")
#define CP_WAIT0   asm volatile("cp.async.wait_group 0;" ::: "memory")
#define CP_WAIT1   asm volatile("cp.async.wait_group 1;" ::: "memory")

__device__ __forceinline__ uint32_t packbf2(float x, float y) {
    __nv_bfloat162 t = __floats2bfloat162_rn(x, y);
    return *(uint32_t*)&t;
}

// ================= flash attention =================
// grid (S_/128, B_*H_), 256 thr (8 warps x m16). Q hi/lo resident in smem,
// K double-buffered, V^T single-buffered, cp.async staggered pipeline.
#define QBLK   128
#define KVBLK  32
#define NKVT   (S_/KVBLK)
#define FO_QL  65536
#define FO_K0  131072
#define FO_V   196608
#define F_SMEM 229376

__global__ void __launch_bounds__(256)
flash_kernel(const bf16* __restrict__ qh_g, const bf16* __restrict__ ql_g,
             const bf16* __restrict__ kh_g, const bf16* __restrict__ kl_g,
             const bf16* __restrict__ vth_g, const bf16* __restrict__ vtl_g,
             bf16* __restrict__ oh_g, bf16* __restrict__ ol_g)
{
    extern __shared__ __align__(128) char sm[];
    const uint32_t sb = smem_u32(sm);
    const int tid = threadIdx.x, wid = tid >> 5, lane = tid & 31;
    const int bh = blockIdx.y;
    const int b = bh >> 3, hd = bh & 7;
    const int q0 = blockIdx.x * QBLK;

    // ---- prologue: Q + K0 + V0 (one group) ----
    #pragma unroll
    for (int it = 0; it < 32; it++) {                 // Q: 8192 x 16B
        int c = tid + it * 256;
        int split = c >> 12; int cc = c & 4095;
        int row = cc >> 5, kc = cc & 31;
        const bf16* src = (split ? ql_g : qh_g)
            + ((size_t)(b * S_ + q0 + row) * INNER_ + hd * 256 + kc * 8);
        CP16(sb + split * 65536 + row * 512 + (uint32_t)((kc ^ (row & 7)) << 4), src);
    }
    #pragma unroll
    for (int it = 0; it < 8; it++) {                  // K0: 2048 x 16B
        int c = tid + it * 256;
        int split = c >> 10; int cc = c & 1023;
        int row = cc >> 5, kc = cc & 31;
        const bf16* src = (split ? kl_g : kh_g)
            + ((size_t)(b * S_ + row) * INNER_ + hd * 256 + kc * 8);
        CP16(sb + FO_K0 + split * 16384 + row * 512 + (uint32_t)((kc ^ (row & 7)) << 4), src);
    }
    #pragma unroll
    for (int it = 0; it < 8; it++) {                  // V0: 2048 x 16B
        int c = tid + it * 256;
        int split = c >> 10; int cc = c & 1023;
        int row = cc >> 2, kc = cc & 3;
        const bf16* src = (split ? vtl_g : vth_g)
            + ((size_t)bh * DH_ * S_ + (size_t)row * S_ + kc * 8);
        CP16(sb + FO_V + split * 16384 + row * 64 + (uint32_t)(((kc ^ ((row >> 1) & 3)) << 4)), src);
    }
    CP_COMMIT;

    const int wm    = wid * 16;
    const int a_row = wm + (lane & 15);
    const uint32_t a_rowoff = (uint32_t)(a_row * 512);
    const int a_r7  = a_row & 7;
    const int a_hb  = lane >> 4;
    const int b_row = (lane & 7) + ((lane >> 4) & 1) * 8;
    const int b_kb  = (lane >> 3) & 1;

    float o[32][4];
    #pragma unroll
    for (int i = 0; i < 32; i++) { o[i][0]=0.f; o[i][1]=0.f; o[i][2]=0.f; o[i][3]=0.f; }
    float m0 = -1e30f, m1 = -1e30f, l0 = 0.f, l1 = 0.f;

    for (int i = 0; i < NKVT; i++) {
        if (i == 0) { CP_WAIT0; } else { CP_WAIT1; }
        __syncthreads();
        const uint32_t kbs = sb + FO_K0 + (uint32_t)((i & 1) * 32768);

        if (i + 1 < NKVT) {                            // issue K(i+1)
            const int kvn = (i + 1) * KVBLK;
            const uint32_t kdst = sb + FO_K0 + (uint32_t)(((i + 1) & 1) * 32768);
            #pragma unroll
            for (int it = 0; it < 8; it++) {
                int c = tid + it * 256;
                int split = c >> 10; int cc = c & 1023;
                int row = cc >> 5, kc = cc & 31;
                const bf16* src = (split ? kl_g : kh_g)
                    + ((size_t)(b * S_ + kvn + row) * INNER_ + hd * 256 + kc * 8);
                CP16(kdst + split * 16384 + row * 512 + (uint32_t)((kc ^ (row & 7)) << 4), src);
            }
            CP_COMMIT;
        }

        // ==== S = (Qh+Ql)(Kh+Kl)^T ====
        float s[4][4];
        #pragma unroll
        for (int nt = 0; nt < 4; nt++) { s[nt][0]=0.f; s[nt][1]=0.f; s[nt][2]=0.f; s[nt][3]=0.f; }
        #pragma unroll
        for (int ks = 0; ks < 16; ks++) {
            const uint32_t aq = a_rowoff + (uint32_t)((((2 * ks + a_hb) ^ a_r7) << 4));
            uint32_t ah4[4], al4[4];
            ldsm_x4(ah4, sb + aq);
            ldsm_x4(al4, sb + FO_QL + aq);
            uint32_t kh4[2][4], kl4[2][4];
            #pragma unroll
            for (int g2 = 0; g2 < 2; g2++) {
                const int row = g2 * 16 + b_row;
                const uint32_t off = (uint32_t)(row * 512 + (((2 * ks + b_kb) ^ (row & 7)) << 4));
                ldsm_x4(kh4[g2], kbs + off);
                ldsm_x4(kl4[g2], kbs + 16384 + off);
            }
            #pragma unroll
            for (int nt = 0; nt < 4; nt++) {
                mma16816(s[nt], ah4, kh4[nt >> 1][(nt & 1) * 2], kh4[nt >> 1][(nt & 1) * 2 + 1]);
                mma16816(s[nt], ah4, kl4[nt >> 1][(nt & 1) * 2], kl4[nt >> 1][(nt & 1) * 2 + 1]);
                mma16816(s[nt], al4, kh4[nt >> 1][(nt & 1) * 2], kh4[nt >> 1][(nt & 1) * 2 + 1]);
            }
        }

        // ==== online softmax (rows g=lane>>2, g+8) ====
        float mx0 = -1e30f, mx1 = -1e30f;
        #pragma unroll
        for (int nt = 0; nt < 4; nt++) {
            s[nt][0] *= 0.0625f; s[nt][1] *= 0.0625f;
            s[nt][2] *= 0.0625f; s[nt][3] *= 0.0625f;
            mx0 = fmaxf(mx0, fmaxf(s[nt][0], s[nt][1]));
            mx1 = fmaxf(mx1, fmaxf(s[nt][2], s[nt][3]));
        }
        mx0 = fmaxf(mx0, __shfl_xor_sync(0xffffffffu, mx0, 1));
        mx0 = fmaxf(mx0, __shfl_xor_sync(0xffffffffu, mx0, 2));
        mx1 = fmaxf(mx1, __shfl_xor_sync(0xffffffffu, mx1, 1));
        mx1 = fmaxf(mx1, __shfl_xor_sync(0xffffffffu, mx1, 2));
        const float mn0 = fmaxf(m0, mx0), mn1 = fmaxf(m1, mx1);
        const float sc0 = __expf(m0 - mn0), sc1 = __expf(m1 - mn1);
        m0 = mn0; m1 = mn1;
        l0 *= sc0; l1 *= sc1;
        if (sc0 != 1.f || sc1 != 1.f) {
            #pragma unroll
            for (int nt = 0; nt < 32; nt++) {
                o[nt][0] *= sc0; o[nt][1] *= sc0;
                o[nt][2] *= sc1; o[nt][3] *= sc1;
            }
        }
        float rs0 = 0.f, rs1 = 0.f;
        #pragma unroll
        for (int nt = 0; nt < 4; nt++) {
            s[nt][0] = __expf(s[nt][0] - m0);
            s[nt][1] = __expf(s[nt][1] - m0);
            s[nt][2] = __expf(s[nt][2] - m1);
            s[nt][3] = __expf(s[nt][3] - m1);
            rs0 += s[nt][0] + s[nt][1];
            rs1 += s[nt][2] + s[nt][3];
        }
        rs0 += __shfl_xor_sync(0xffffffffu, rs0, 1);
        rs0 += __shfl_xor_sync(0xffffffffu, rs0, 2);
        rs1 += __shfl_xor_sync(0xffffffffu, rs1, 1);
        rs1 += __shfl_xor_sync(0xffffffffu, rs1, 2);
        l0 += rs0; l1 += rs1;

        // P -> bf16 hi/lo A-fragments
        uint32_t pah[2][4], pal[2][4];
        #pragma unroll
        for (int ks = 0; ks < 2; ks++) {
            const int j0 = 2 * ks, j1 = 2 * ks + 1;
            pah[ks][0] = packbf2(s[j0][0], s[j0][1]);
            pah[ks][1] = packbf2(s[j0][2], s[j0][3]);
            pah[ks][2] = packbf2(s[j1][0], s[j1][1]);
            pah[ks][3] = packbf2(s[j1][2], s[j1][3]);
            __nv_bfloat162 h0 = *(__nv_bfloat162*)&pah[ks][0];
            __nv_bfloat162 h1 = *(__nv_bfloat162*)&pah[ks][1];
            __nv_bfloat162 h2 = *(__nv_bfloat162*)&pah[ks][2];
            __nv_bfloat162 h3 = *(__nv_bfloat162*)&pah[ks][3];
            pal[ks][0] = packbf2(s[j0][0] - __bfloat162float(__low2bfloat16(h0)),
                                 s[j0][1] - __bfloat162float(__high2bfloat16(h0)));
            pal[ks][1] = packbf2(s[j0][2] - __bfloat162float(__low2bfloat16(h1)),
                                 s[j0][3] - __bfloat162float(__high2bfloat16(h1)));
            pal[ks][2] = packbf2(s[j1][0] - __bfloat162float(__low2bfloat16(h2)),
                                 s[j1][1] - __bfloat162float(__high2bfloat16(h2)));
            pal[ks][3] = packbf2(s[j1][2] - __bfloat162float(__low2bfloat16(h3)),
                                 s[j1][3] - __bfloat162float(__high2bfloat16(h3)));
        }

        if (i + 1 < NKVT) { CP_WAIT1; } else { CP_WAIT0; }   // V(i) landed
        __syncthreads();

        // ==== O += P(hi/lo) @ V(hi/lo) ====
        #pragma unroll
        for (int half = 0; half < 2; half++) {
            #pragma unroll
            for (int ks = 0; ks < 2; ks++) {
                #pragma unroll
                for (int j2 = 0; j2 < 8; j2++) {
                    const int row = half * 128 + j2 * 16 + b_row;
                    const uint32_t voff = (uint32_t)(row * 64 +
                        (((2 * ks + b_kb) ^ ((row >> 1) & 3)) << 4));
                    const int nt = half * 16 + j2 * 2;
                    uint32_t vh4[4], vl4[4];
                    ldsm_x4(vh4, sb + FO_V + voff);
                    mma16816(o[nt],     pah[ks], vh4[0], vh4[1]);
                    mma16816(o[nt + 1], pah[ks], vh4[2], vh4[3]);
                    mma16816(o[nt],     pal[ks], vh4[0], vh4[1]);
                    mma16816(o[nt + 1], pal[ks], vh4[2], vh4[3]);
                    ldsm_x4(vl4, sb + FO_V + 16384 + voff);
                    mma16816(o[nt],     pah[ks], vl4[0], vl4[1]);
                    mma16816(o[nt + 1], pah[ks], vl4[2], vl4[3]);
                }
            }
        }
        __syncthreads();

        if (i + 1 < NKVT) {                            // issue V(i+1)
            const int kvn = (i + 1) * KVBLK;
            #pragma unroll
            for (int it = 0; it < 8; it++) {
                int c = tid + it * 256;
                int split = c >> 10; int cc = c & 1023;
                int row = cc >> 2, kc = cc & 3;
                const bf16* src = (split ? vtl_g : vth_g)
                    + ((size_t)bh * DH_ * S_ + (size_t)row * S_ + kvn + kc * 8);
                CP16(sb + FO_V + split * 16384 + row * 64 +
                     (uint32_t)((kc ^ ((row >> 1) & 3)) << 4), src);
            }
            CP_COMMIT;
        }
    }

    // ==== normalize + split-store O ====
    const float inv0 = 1.f / l0, inv1 = 1.f / l1;
    const int g  = lane >> 2;
    const int t2 = (lane & 3) * 2;
    const size_t base0 = (size_t)(b * S_ + q0 + wm + g) * INNER_ + hd * 256 + t2;
    const size_t base1 = base0 + (size_t)8 * INNER_;
    #pragma unroll
    for (int nt = 0; nt < 32; nt++) {
        float v0 = o[nt][0] * inv0, v1 = o[nt][1] * inv0;
        float v2 = o[nt][2] * inv1, v3 = o[nt][3] * inv1;
        uint32_t h0 = packbf2(v0, v1);
        uint32_t h2 = packbf2(v2, v3);
        __nv_bfloat162 hh0 = *(__nv_bfloat162*)&h0;
        __nv_bfloat162 hh2 = *(__nv_bfloat162*)&h2;
        uint32_t lo0 = packbf2(v0 - __bfloat162float(__low2bfloat16(hh0)),
                               v1 - __bfloat162float(__high2bfloat16(hh0)));
        uint32_t lo2 = packbf2(v2 - __bfloat162float(__low2bfloat16(hh2)),
                               v3 - __bfloat162float(__high2bfloat16(hh2)));
        *(uint32_t*)&oh_g[base0 + (size_t)nt * 8] = h0;
        *(uint32_t*)&ol_g[base0 + (size_t)nt * 8] = lo0;
        *(uint32_t*)&oh_g[base1 + (size_t)nt * 8] = h2;
        *(uint32_t*)&ol_g[base1 + (size_t)nt * 8] = lo2;
    }
}

// ---------------- bf16x3 HMMA GEMM (verified round 4) ----------------
#define KB_   32
#define ASTR  80

template<int OUT_SPLIT>
__global__ void __launch_bounds__(256)
gemm_hmma3(const bf16* __restrict__ Ah, const bf16* __restrict__ Al, int lda,
           const bf16* __restrict__ Bh, const bf16* __restrict__ Bl, int ldb,
           float* __restrict__ Cf, bf16* __restrict__ Ch, bf16* __restrict__ Cl, int ldc,
           int K, int zdiv,
           long long sA1, long long sA2,
           long long sB1, long long sB2,
           long long sC1, long long sC2,
           const float* __restrict__ bias,
           const float* __restrict__ resid, int ldr,
           float alpha, int relu)
{
    __shared__ __align__(16) char sAh[128 * ASTR];
    __shared__ __align__(16) char sAl[128 * ASTR];
    __shared__ __align__(16) char sBh[128 * ASTR];
    __shared__ __align__(16) char sBl[128 * ASTR];

    const int z  = blockIdx.z;
    const int zq = z / zdiv, zr = z % zdiv;
    const long long aoff = (long long)zq * sA1 + (long long)zr * sA2;
    const long long boff = (long long)zq * sB1 + (long long)zr * sB2;
    const long long coff = (long long)zq * sC1 + (long long)zr * sC2;
    Ah += aoff; Al += aoff;
    Bh += boff; Bl += boff;
    if (Cf) Cf += coff;
    if (Ch) { Ch += coff; Cl += coff; }

    const int bm   = blockIdx.y * 128;
    const int bn   = blockIdx.x * 128;
    const int tid  = threadIdx.x;
    const int wid  = tid >> 5;
    const int lane = tid & 31;
    const int wm   = (wid & 1) * 64;
    const int wn   = (wid >> 1) * 32;

    const int lrow0 = tid >> 2;
    const int lrow1 = (tid + 256) >> 2;
    const int lc0   = tid & 3;

    const uint32_t uAh = smem_u32(sAh);
    const uint32_t uAl = smem_u32(sAl);
    const uint32_t uBh = smem_u32(sBh);
    const uint32_t uBl = smem_u32(sBl);

    const uint32_t aBase = (uint32_t)((wm + (lane & 15)) * ASTR + (lane >> 4) * 16);
    const uint32_t bBase = (uint32_t)((wn + (lane & 7) + ((lane >> 4) & 1) * 8) * ASTR
                                      + (lane & 8) * 2);

    float acc[4][4][4];
    #pragma unroll
    for (int mt = 0; mt < 4; mt++)
        #pragma unroll
        for (int nt = 0; nt < 4; nt++)
            #pragma unroll
            for (int i = 0; i < 4; i++) acc[mt][nt][i] = 0.f;

    uint4 pAh[2], pAl[2], pBh[2], pBl[2];
    {
        const long long ga0 = (long long)(bm + lrow0) * lda + lc0 * 8;
        const long long ga1 = (long long)(bm + lrow1) * lda + lc0 * 8;
        const long long gb0 = (long long)(bn + lrow0) * ldb + lc0 * 8;
        const long long gb1 = (long long)(bn + lrow1) * ldb + lc0 * 8;
        pAh[0] = *(const uint4*)(Ah + ga0); pAh[1] = *(const uint4*)(Ah + ga1);
        pAl[0] = *(const uint4*)(Al + ga0); pAl[1] = *(const uint4*)(Al + ga1);
        pBh[0] = *(const uint4*)(Bh + gb0); pBh[1] = *(const uint4*)(Bh + gb1);
        pBl[0] = *(const uint4*)(Bl + gb0); pBl[1] = *(const uint4*)(Bl + gb1);
    }

    const int nkb = K / KB_;
    for (int kb = 0; kb < nkb; kb++) {
        const int so0 = lrow0 * ASTR + lc0 * 16;
        const int so1 = lrow1 * ASTR + lc0 * 16;
        *(uint4*)(sAh + so0) = pAh[0]; *(uint4*)(sAh + so1) = pAh[1];
        *(uint4*)(sAl + so0) = pAl[0]; *(uint4*)(sAl + so1) = pAl[1];
        *(uint4*)(sBh + so0) = pBh[0]; *(uint4*)(sBh + so1) = pBh[1];
        *(uint4*)(sBl + so0) = pBl[0]; *(uint4*)(sBl + so1) = pBl[1];
        __syncthreads();

        if (kb + 1 < nkb) {
            const int kn = (kb + 1) * KB_;
            const long long ga0 = (long long)(bm + lrow0) * lda + kn + lc0 * 8;
            const long long ga1 = (long long)(bm + lrow1) * lda + kn + lc0 * 8;
            const long long gb0 = (long long)(bn + lrow0) * ldb + kn + lc0 * 8;
            const long long gb1 = (long long)(bn + lrow1) * ldb + kn + lc0 * 8;
            pAh[0] = *(const uint4*)(Ah + ga0); pAh[1] = *(const uint4*)(Ah + ga1);
            pAl[0] = *(const uint4*)(Al + ga0); pAl[1] = *(const uint4*)(Al + ga1);
            pBh[0] = *(const uint4*)(Bh + gb0); pBh[1] = *(const uint4*)(Bh + gb1);
            pBl[0] = *(const uint4*)(Bl + gb0); pBl[1] = *(const uint4*)(Bl + gb1);
        }

        #pragma unroll
        for (int ks = 0; ks < 2; ks++) {
            const uint32_t ksb = ks * 32;
            uint32_t ah[4][4], al[4][4];
            #pragma unroll
            for (int mt = 0; mt < 4; mt++) {
                ldsm_x4(ah[mt], uAh + aBase + mt * (16 * ASTR) + ksb);
                ldsm_x4(al[mt], uAl + aBase + mt * (16 * ASTR) + ksb);
            }
            uint32_t bh[2][4], bl[2][4];
            #pragma unroll
            for (int g = 0; g < 2; g++) {
                ldsm_x4(bh[g], uBh + bBase + g * (16 * ASTR) + ksb);
                ldsm_x4(bl[g], uBl + bBase + g * (16 * ASTR) + ksb);
            }
            #pragma unroll
            for (int mt = 0; mt < 4; mt++) {
                #pragma unroll
                for (int nt = 0; nt < 4; nt++) {
                    const uint32_t b0h = bh[nt >> 1][(nt & 1) * 2];
                    const uint32_t b1h = bh[nt >> 1][(nt & 1) * 2 + 1];
                    const uint32_t b0l = bl[nt >> 1][(nt & 1) * 2];
                    const uint32_t b1l = bl[nt >> 1][(nt & 1) * 2 + 1];
                    mma16816(acc[mt][nt], ah[mt], b0h, b1h);
                    mma16816(acc[mt][nt], ah[mt], b0l, b1l);
                    mma16816(acc[mt][nt], al[mt], b0h, b1h);
                }
            }
        }
        __syncthreads();
    }

    const int er = lane >> 2;
    const int ec = (lane & 3) * 2;
    #pragma unroll
    for (int mt = 0; mt < 4; mt++) {
        #pragma unroll
        for (int half = 0; half < 2; half++) {
            const int m = bm + wm + mt * 16 + er + half * 8;
            #pragma unroll
            for (int nt = 0; nt < 4; nt++) {
                const int n = bn + wn + nt * 8 + ec;
                float v0 = acc[mt][nt][half * 2 + 0] * alpha;
                float v1 = acc[mt][nt][half * 2 + 1] * alpha;
                if (bias) { v0 += __ldg(&bias[n]); v1 += __ldg(&bias[n + 1]); }
                if (resid) {
                    float2 rr = *(const float2*)&resid[(long long)m * ldr + n];
                    v0 += rr.x; v1 += rr.y;
                }
                if (relu) { v0 = fmaxf(v0, 0.f); v1 = fmaxf(v1, 0.f); }
                if (OUT_SPLIT) {
                    __nv_bfloat162 hi2 = __floats2bfloat162_rn(v0, v1);
                    float l0 = v0 - __bfloat162float(__low2bfloat16(hi2));
                    float l1 = v1 - __bfloat162float(__high2bfloat16(hi2));
                    __nv_bfloat162 lo2 = __floats2bfloat162_rn(l0, l1);
                    *(uint32_t*)&Ch[(long long)m * ldc + n] = *(uint32_t*)&hi2;
                    *(uint32_t*)&Cl[(long long)m * ldc + n] = *(uint32_t*)&lo2;
                } else {
                    *(float2*)&Cf[(long long)m * ldc + n] = make_float2(v0, v1);
                }
            }
        }
    }
}

// ---------------- reductions ----------------
__device__ __forceinline__ float warp_sum(float v) {
    #pragma unroll
    for (int o = 16; o > 0; o >>= 1) v += __shfl_xor_sync(0xffffffffu, v, o);
    return v;
}
__device__ __forceinline__ float block_reduce_sum(float v) {
    __shared__ float sm2[32];
    __shared__ float res;
    int lane = threadIdx.x & 31;
    int wid  = threadIdx.x >> 5;
    v = warp_sum(v);
    __syncthreads();
    if (lane == 0) sm2[wid] = v;
    __syncthreads();
    if (wid == 0) {
        int nw = blockDim.x >> 5;
        float x = (lane < nw) ? sm2[lane] : 0.f;
        x = warp_sum(x);
        if (lane == 0) res = x;
    }
    __syncthreads();
    return res;
}

// ---------------- layernorm ----------------
__global__ void ln_kernel(const float* __restrict__ x,
                          const float* __restrict__ g,
                          const float* __restrict__ b,
                          float* __restrict__ outf,
                          bf16* __restrict__ oh, bf16* __restrict__ ol)
{
    const int t = threadIdx.x;
    const long long base = (long long)blockIdx.x * E_;
    float v = x[base + t];
    float mean = block_reduce_sum(v) * (1.f / E_);
    float d = v - mean;
    float var = block_reduce_sum(d * d) * (1.f / E_);
    float r = d * rsqrtf(var + EPS_) * g[t] + b[t];
    if (outf) outf[base + t] = r;
    if (oh) {
        bf16 hi = __float2bfloat16(r);
        oh[base + t] = hi;
        ol[base + t] = __float2bfloat16(r - __bfloat162float(hi));
    }
}

// ---------------- fp32 -> bf16 hi/lo split ----------------
__global__ void split_kernel(const float* __restrict__ in,
                             bf16* __restrict__ oh, bf16* __restrict__ ol, int n)
{
    int i = blockIdx.x * blockDim.x + threadIdx.x;
    if (i < n) {
        float f = in[i];
        bf16 hi = __float2bfloat16(f);
        oh[i] = hi;
        ol[i] = __float2bfloat16(f - __bfloat162float(hi));
    }
}

// ---------------- weight transpose + split ----------------
__global__ void wsplitT_kernel(const float* __restrict__ W, int R, int C,
                               bf16* __restrict__ oh, bf16* __restrict__ ol)
{
    __shared__ float t[32][33];
    const int c0 = blockIdx.x * 32;
    const int r0 = blockIdx.y * 32;
    const int tx = threadIdx.x, ty = threadIdx.y;
    #pragma unroll
    for (int j = 0; j < 4; j++) {
        int r = ty + 8 * j;
        t[r][tx] = W[(long long)(r0 + r) * C + c0 + tx];
    }
    __syncthreads();
    #pragma unroll
    for (int j = 0; j < 4; j++) {
        int r = ty + 8 * j;
        float f = t[tx][r];
        bf16 hi = __float2bfloat16(f);
        long long o = (long long)(c0 + r) * R + r0 + tx;
        oh[o] = hi;
        ol[o] = __float2bfloat16(f - __bfloat162float(hi));
    }
}

// ---------------- V transpose ----------------
__global__ void vtrans_kernel(const bf16* __restrict__ vh, const bf16* __restrict__ vl,
                              bf16* __restrict__ vth, bf16* __restrict__ vtl)
{
    __shared__ bf16 th[32][33];
    __shared__ bf16 tl[32][33];
    const int z = blockIdx.z;
    const int b = z / H_, h = z % H_;
    const int s0 = blockIdx.x * 32;
    const int d0 = blockIdx.y * 32;
    const int tx = threadIdx.x, ty = threadIdx.y;
    const long long ibase = (long long)b * S_ * INNER_ + (long long)h * DH_;
    const long long obase = (long long)z * DH_ * S_;
    #pragma unroll
    for (int j = 0; j < 4; j++) {
        int r = ty + 8 * j;
        long long ia = ibase + (long long)(s0 + r) * INNER_ + d0 + tx;
        th[r][tx] = vh[ia];
        tl[r][tx] = vl[ia];
    }
    __syncthreads();
    #pragma unroll
    for (int j = 0; j < 4; j++) {
        int r = ty + 8 * j;
        long long oa = obase + (long long)(d0 + r) * S_ + s0 + tx;
        vth[oa] = th[tx][r];
        vtl[oa] = tl[tx][r];
    }
}

// ---------------- launch ----------------
extern "C" void kernel_launch(void* const* d_in, const int* in_sizes, int n_in,
                              void* d_out, int out_size)
{
    const float* x    = (const float*)d_in[0];
    const float* Wq   = (const float*)d_in[1];
    const float* Wk   = (const float*)d_in[2];
    const float* Wv   = (const float*)d_in[3];
    const float* Wo   = (const float*)d_in[4];
    const float* W1   = (const float*)d_in[5];
    const float* b1   = (const float*)d_in[6];
    const float* W2   = (const float*)d_in[7];
    const float* b2   = (const float*)d_in[8];
    const float* ln1g = (const float*)d_in[9];
    const float* ln1b = (const float*)d_in[10];
    const float* ln2g = (const float*)d_in[11];
    const float* ln2b = (const float*)d_in[12];

    #define SYM(p, s) p; cudaGetSymbolAddress((void**)&p, s)
    bf16 *SYM(xh, g_xh); bf16 *SYM(xl, g_xl);
    bf16 *SYM(wqh, g_wqT_h); bf16 *SYM(wql, g_wqT_l);
    bf16 *SYM(wkh, g_wkT_h); bf16 *SYM(wkl, g_wkT_l);
    bf16 *SYM(wvh, g_wvT_h); bf16 *SYM(wvl, g_wvT_l);
    bf16 *SYM(woh, g_woT_h); bf16 *SYM(wol, g_woT_l);
    bf16 *SYM(w1h, g_w1T_h); bf16 *SYM(w1l, g_w1T_l);
    bf16 *SYM(w2h, g_w2T_h); bf16 *SYM(w2l, g_w2T_l);
    bf16 *SYM(qh, g_qh); bf16 *SYM(ql, g_ql);
    bf16 *SYM(kh, g_kh); bf16 *SYM(kl, g_kl);
    bf16 *SYM(vh, g_vh); bf16 *SYM(vl, g_vl);
    bf16 *SYM(vth, g_vth); bf16 *SYM(vtl, g_vtl);
    bf16 *SYM(oh, g_oh); bf16 *SYM(ol, g_ol);
    float *SYM(t1, g_t1); float *SYM(hf, g_hf);
    bf16 *SYM(hh, g_hh); bf16 *SYM(hl, g_hl);
    bf16 *SYM(ffh, g_ffh); bf16 *SYM(ffl, g_ffl);
    float *SYM(t2, g_t2);

    cudaFuncSetAttribute(flash_kernel, cudaFuncAttributeMaxDynamicSharedMemorySize, F_SMEM);

    const dim3 blk(256);
    const dim3 tblk(32, 8);

    // 0) splits / transposed weights
    split_kernel<<<(BSZ * E_ + 255) / 256, 256>>>(x, xh, xl, BSZ * E_);
    { dim3 g(INNER_/32, E_/32);  wsplitT_kernel<<<g, tblk>>>(Wq, E_, INNER_, wqh, wql); }
    { dim3 g(INNER_/32, E_/32);  wsplitT_kernel<<<g, tblk>>>(Wk, E_, INNER_, wkh, wkl); }
    { dim3 g(INNER_/32, E_/32);  wsplitT_kernel<<<g, tblk>>>(Wv, E_, INNER_, wvh, wvl); }
    { dim3 g(E_/32, INNER_/32);  wsplitT_kernel<<<g, tblk>>>(Wo, INNER_, E_, woh, wol); }
    { dim3 g(DFF_/32, E_/32);    wsplitT_kernel<<<g, tblk>>>(W1, E_, DFF_, w1h, w1l); }
    { dim3 g(E_/32, DFF_/32);    wsplitT_kernel<<<g, tblk>>>(W2, DFF_, E_, w2h, w2l); }

    // 1) QKV projections
    {
        dim3 grd(INNER_/128, BSZ/128, 1);
        gemm_hmma3<1><<<grd, blk>>>(xh, xl, E_, wqh, wql, E_,
            nullptr, qh, ql, INNER_, E_, 1, 0,0, 0,0, 0,0,
            nullptr, nullptr, 0, 1.f, 0);
        gemm_hmma3<1><<<grd, blk>>>(xh, xl, E_, wkh, wkl, E_,
            nullptr, kh, kl, INNER_, E_, 1, 0,0, 0,0, 0,0,
            nullptr, nullptr, 0, 1.f, 0);
        gemm_hmma3<1><<<grd, blk>>>(xh, xl, E_, wvh, wvl, E_,
            nullptr, vh, vl, INNER_, E_, 1, 0,0, 0,0, 0,0,
            nullptr, nullptr, 0, 1.f, 0);
    }

    // 2) V^T per (b,h)
    { dim3 g(S_/32, DH_/32, B_*H_); vtrans_kernel<<<g, tblk>>>(vh, vl, vth, vtl); }

    // 3) fused flash attention -> O (split)
    {
        dim3 grd(S_/QBLK, B_*H_);
        flash_kernel<<<grd, blk, F_SMEM>>>(qh, ql, kh, kl, vth, vtl, oh, ol);
    }

    // 4) t1 = O @ Wo + x ; h = LN1
    {
        dim3 grd(E_/128, BSZ/128, 1);
        gemm_hmma3<0><<<grd, blk>>>(oh, ol, INNER_, woh, wol, INNER_,
            t1, nullptr, nullptr, E_, INNER_, 1, 0,0, 0,0, 0,0,
            nullptr, x, E_, 1.f, 0);
        ln_kernel<<<BSZ, 256>>>(t1, ln1g, ln1b, hf, hh, hl);
    }

    // 5) ff = relu(h @ W1 + b1)
    {
        dim3 grd(DFF_/128, BSZ/128, 1);
        gemm_hmma3<1><<<grd, blk>>>(hh, hl, E_, w1h, w1l, E_,
            nullptr, ffh, ffl, DFF_, E_, 1, 0,0, 0,0, 0,0,
            b1, nullptr, 0, 1.f, 1);
    }

    // 6) t2 = ff @ W2 + b2 + h ; out = LN2
    {
        dim3 grd(E_/128, BSZ/128, 1);
        gemm_hmma3<0><<<grd, blk>>>(ffh, ffl, DFF_, w2h, w2l, DFF_,
            t2, nullptr, nullptr, E_, DFF_, 1, 0,0, 0,0, 0,0,
            b2, hf, E_, 1.f, 0);
        ln_kernel<<<BSZ, 256>>>(t2, ln2g, ln2b, (float*)d_out, nullptr, nullptr);
    }
}